// round 2
// baseline (speedup 1.0000x reference)
#include <cuda_runtime.h>

// Problem constants
#define SQ   2048
#define DIM  768
#define NH   12
#define DH   64
#define NB   2
#define BH   (NB*NH)   // 24

// Scratch: [5][BH][S][DH] fp32 = 60 MB (device global: allocation-free)
__device__ float g_proj[5u * BH * SQ * DH];

// ---------------------------------------------------------------------------
// Kernel 1: fused projections.  out[n,o] = dot(X[n,:], W[o,:])  (y = x @ W^T)
// Tiles: 128x128xK8, 256 threads, 8x8 per thread (split 4+4 register blocking).
// Grid: x = 30 (5 weights * 6 col-blocks), y = 32 row-blocks.
// ---------------------------------------------------------------------------
__global__ __launch_bounds__(256) void proj_kernel(
    const float* __restrict__ X,
    const float* __restrict__ W0, const float* __restrict__ W1,
    const float* __restrict__ W2, const float* __restrict__ W3,
    const float* __restrict__ W4)
{
    __shared__ float As[8][128];
    __shared__ float Bs[8][128];

    const int bx      = blockIdx.x;
    const int which   = bx / 6;
    const int colBase = (bx % 6) * 128;     // within [0,768)
    const int rowBase = blockIdx.y * 128;   // within [0,4096)
    const float* W = (which == 0) ? W0 : (which == 1) ? W1 :
                     (which == 2) ? W2 : (which == 3) ? W3 : W4;

    const int tid = threadIdx.x;
    const int tx  = tid & 15;
    const int ty  = tid >> 4;
    const int lr  = tid >> 1;          // 0..127
    const int lk  = (tid & 1) * 4;     // 0 or 4

    const float* Ag = X + (size_t)(rowBase + lr) * DIM + lk;
    const float* Bg = W + (size_t)(colBase + lr) * DIM + lk;

    float acc[8][8];
    #pragma unroll
    for (int i = 0; i < 8; i++)
        #pragma unroll
        for (int j = 0; j < 8; j++) acc[i][j] = 0.f;

    for (int k0 = 0; k0 < DIM; k0 += 8) {
        float4 a = *(const float4*)(Ag + k0);
        float4 b = *(const float4*)(Bg + k0);
        As[lk+0][lr] = a.x; As[lk+1][lr] = a.y; As[lk+2][lr] = a.z; As[lk+3][lr] = a.w;
        Bs[lk+0][lr] = b.x; Bs[lk+1][lr] = b.y; Bs[lk+2][lr] = b.z; Bs[lk+3][lr] = b.w;
        __syncthreads();
        #pragma unroll
        for (int k = 0; k < 8; k++) {
            float ar[8], br[8];
            #pragma unroll
            for (int i = 0; i < 4; i++) {
                ar[i]   = As[k][ty*4 + i];
                ar[4+i] = As[k][64 + ty*4 + i];
            }
            #pragma unroll
            for (int j = 0; j < 4; j++) {
                br[j]   = Bs[k][tx*4 + j];
                br[4+j] = Bs[k][64 + tx*4 + j];
            }
            #pragma unroll
            for (int i = 0; i < 8; i++)
                #pragma unroll
                for (int j = 0; j < 8; j++)
                    acc[i][j] = fmaf(ar[i], br[j], acc[i][j]);
        }
        __syncthreads();
    }

    // Write into [which][b*H+h][s][d] layout
    #pragma unroll
    for (int i = 0; i < 8; i++) {
        int r  = rowBase + ty*4 + (i & 3) + ((i >= 4) ? 64 : 0);
        int b_ = r >> 11;            // /2048
        int s_ = r & (SQ - 1);
        #pragma unroll
        for (int j = 0; j < 8; j++) {
            int oo = colBase + tx*4 + (j & 3) + ((j >= 4) ? 64 : 0);
            int h  = oo >> 6;
            int d  = oo & 63;
            g_proj[(((size_t)which * BH + (b_ * NH + h)) * SQ + s_) * DH + d] = acc[i][j];
        }
    }
}

// ---------------------------------------------------------------------------
// Kernel 2: fused complex attention (flash-style online softmax).
// CTA = (64 q-rows) x (one bh).  256 threads as 16x16, 4x4 accum per thread.
// Score columns per thread: tx + 16*j (conflict-free kr/ki fragment loads).
// Output d-columns per thread: tx*4 + j (conflict-free v loads, vector store).
// ---------------------------------------------------------------------------
#define PAD 68

__global__ __launch_bounds__(256) void attn_kernel(float* __restrict__ out)
{
    extern __shared__ float sm[];
    float* qr_s = sm;
    float* qi_s = qr_s + 64*PAD;
    float* kr_s = qi_s + 64*PAD;
    float* ki_s = kr_s + 64*PAD;
    float* v_s  = ki_s + 64*PAD;
    float* p_s  = v_s  + 64*PAD;

    const int tid = threadIdx.x;
    const int tx  = tid & 15;
    const int ty  = tid >> 4;
    const int bh  = blockIdx.y;
    const int q0  = blockIdx.x * 64;

    const float* Qr = g_proj + ((size_t)(0*BH + bh) * SQ + q0) * DH;
    const float* Qi = g_proj + ((size_t)(1*BH + bh) * SQ + q0) * DH;

    // Load Q tiles (contiguous 4096 floats each)
    #pragma unroll
    for (int t = 0; t < 4; t++) {
        int idx = tid + t*256;
        int r = idx >> 4;
        int c = (idx & 15) << 2;
        *(float4*)&qr_s[r*PAD + c] = *(const float4*)&Qr[idx*4];
        *(float4*)&qi_s[r*PAD + c] = *(const float4*)&Qi[idx*4];
    }

    float o[16];
    float m[4], l[4];
    #pragma unroll
    for (int i = 0; i < 16; i++) o[i] = 0.f;
    #pragma unroll
    for (int i = 0; i < 4; i++) { m[i] = -1e30f; l[i] = 0.f; }

    const float scale = 0.125f;  // 1/sqrt(64)

    for (int kt = 0; kt < SQ/64; kt++) {
        const float* Kr = g_proj + ((size_t)(2*BH + bh) * SQ + kt*64) * DH;
        const float* Ki = g_proj + ((size_t)(3*BH + bh) * SQ + kt*64) * DH;
        const float* Vv = g_proj + ((size_t)(4*BH + bh) * SQ + kt*64) * DH;
        #pragma unroll
        for (int t = 0; t < 4; t++) {
            int idx = tid + t*256;
            int r = idx >> 4;
            int c = (idx & 15) << 2;
            *(float4*)&kr_s[r*PAD + c] = *(const float4*)&Kr[idx*4];
            *(float4*)&ki_s[r*PAD + c] = *(const float4*)&Ki[idx*4];
            *(float4*)&v_s [r*PAD + c] = *(const float4*)&Vv[idx*4];
        }
        __syncthreads();

        // --- scores: sr = qr.kr + qi.ki ; si = qi.kr - qr.ki ---
        float sr[16], si[16];
        #pragma unroll
        for (int i = 0; i < 16; i++) { sr[i] = 0.f; si[i] = 0.f; }

        #pragma unroll 4
        for (int d0 = 0; d0 < 64; d0 += 4) {
            float4 qrF[4], qiF[4], krF[4], kiF[4];
            #pragma unroll
            for (int i = 0; i < 4; i++) {
                qrF[i] = *(const float4*)&qr_s[(ty*4 + i)*PAD + d0];
                qiF[i] = *(const float4*)&qi_s[(ty*4 + i)*PAD + d0];
            }
            #pragma unroll
            for (int j = 0; j < 4; j++) {
                krF[j] = *(const float4*)&kr_s[(tx + 16*j)*PAD + d0];
                kiF[j] = *(const float4*)&ki_s[(tx + 16*j)*PAD + d0];
            }
            #pragma unroll
            for (int i = 0; i < 4; i++) {
                #pragma unroll
                for (int j = 0; j < 4; j++) {
#define CFMA(C) \
    sr[i*4+j] = fmaf( qrF[i].C, krF[j].C, sr[i*4+j]); \
    sr[i*4+j] = fmaf( qiF[i].C, kiF[j].C, sr[i*4+j]); \
    si[i*4+j] = fmaf( qiF[i].C, krF[j].C, si[i*4+j]); \
    si[i*4+j] = fmaf(-qrF[i].C, kiF[j].C, si[i*4+j]);
                    CFMA(x) CFMA(y) CFMA(z) CFMA(w)
#undef CFMA
                }
            }
        }

        // --- magnitude + online softmax per row ---
        #pragma unroll
        for (int i = 0; i < 4; i++) {
            float s0 = sqrtf(fmaf(sr[i*4+0], sr[i*4+0], si[i*4+0]*si[i*4+0])) * scale;
            float s1 = sqrtf(fmaf(sr[i*4+1], sr[i*4+1], si[i*4+1]*si[i*4+1])) * scale;
            float s2 = sqrtf(fmaf(sr[i*4+2], sr[i*4+2], si[i*4+2]*si[i*4+2])) * scale;
            float s3 = sqrtf(fmaf(sr[i*4+3], sr[i*4+3], si[i*4+3]*si[i*4+3])) * scale;
            float mx = fmaxf(fmaxf(s0, s1), fmaxf(s2, s3));
            #pragma unroll
            for (int off = 8; off >= 1; off >>= 1)
                mx = fmaxf(mx, __shfl_xor_sync(0xffffffffu, mx, off));
            float mnew = fmaxf(m[i], mx);
            float corr = __expf(m[i] - mnew);
            float p0 = __expf(s0 - mnew);
            float p1 = __expf(s1 - mnew);
            float p2 = __expf(s2 - mnew);
            float p3 = __expf(s3 - mnew);
            float* pr = &p_s[(ty*4 + i)*PAD];
            pr[tx] = p0; pr[tx+16] = p1; pr[tx+32] = p2; pr[tx+48] = p3;
            float rs = (p0 + p1) + (p2 + p3);
            #pragma unroll
            for (int off = 8; off >= 1; off >>= 1)
                rs += __shfl_xor_sync(0xffffffffu, rs, off);
            l[i] = l[i]*corr + rs;
            m[i] = mnew;
            o[i*4+0] *= corr; o[i*4+1] *= corr; o[i*4+2] *= corr; o[i*4+3] *= corr;
        }
        __syncthreads();

        // --- O += P @ V ---
        #pragma unroll 4
        for (int k0 = 0; k0 < 64; k0 += 4) {
            float4 pF[4], vF[4];
            #pragma unroll
            for (int i = 0; i < 4; i++)
                pF[i] = *(const float4*)&p_s[(ty*4 + i)*PAD + k0];
            #pragma unroll
            for (int kk = 0; kk < 4; kk++)
                vF[kk] = *(const float4*)&v_s[(k0 + kk)*PAD + tx*4];
            #pragma unroll
            for (int i = 0; i < 4; i++) {
#define PVS(C, jj) \
    o[i*4+jj] = fmaf(pF[i].x, vF[0].C, o[i*4+jj]); \
    o[i*4+jj] = fmaf(pF[i].y, vF[1].C, o[i*4+jj]); \
    o[i*4+jj] = fmaf(pF[i].z, vF[2].C, o[i*4+jj]); \
    o[i*4+jj] = fmaf(pF[i].w, vF[3].C, o[i*4+jj]);
                PVS(x,0) PVS(y,1) PVS(z,2) PVS(w,3)
#undef PVS
            }
        }
        __syncthreads();
    }

    // Epilogue: normalize and write [b, s, h*64+d]
    const int b_ = bh / NH, h = bh % NH;
    #pragma unroll
    for (int i = 0; i < 4; i++) {
        float inv = 1.0f / l[i];
        int row = q0 + ty*4 + i;
        float4 r4 = make_float4(o[i*4+0]*inv, o[i*4+1]*inv, o[i*4+2]*inv, o[i*4+3]*inv);
        *(float4*)&out[((size_t)(b_*SQ + row))*DIM + h*DH + tx*4] = r4;
    }
}

// ---------------------------------------------------------------------------
extern "C" void kernel_launch(void* const* d_in, const int* in_sizes, int n_in,
                              void* d_out, int out_size)
{
    const float* X   = (const float*)d_in[0];
    const float* Wqr = (const float*)d_in[1];
    const float* Wqi = (const float*)d_in[2];
    const float* Wkr = (const float*)d_in[3];
    const float* Wki = (const float*)d_in[4];
    const float* Wv  = (const float*)d_in[5];
    float* out = (float*)d_out;

    const int attn_smem = 6 * 64 * PAD * sizeof(float);  // 104448 B
    cudaFuncSetAttribute(attn_kernel, cudaFuncAttributeMaxDynamicSharedMemorySize, attn_smem);

    proj_kernel<<<dim3(30, 32), 256>>>(X, Wqr, Wqi, Wkr, Wki, Wv);
    attn_kernel<<<dim3(SQ/64, BH), 256, attn_smem>>>(out);
}

// round 3
// speedup vs baseline: 1.0022x; 1.0022x over previous
#include <cuda_runtime.h>

// Problem constants
#define SQ   2048
#define DIM  768
#define NH   12
#define DH   64
#define NB   2
#define BH   (NB*NH)   // 24

// Scratch: [5][BH][S][DH] fp32 = 60 MB (device global: allocation-free)
__device__ float g_proj[5u * BH * SQ * DH];

// ---------------------------------------------------------------------------
// Kernel 1: fused projections.  out[n,o] = dot(X[n,:], W[o,:])  (y = x @ W^T)
// Tiles: 128x128xK8, 256 threads, 8x8 per thread (split 4+4 register blocking).
// Grid: x = 30 (5 weights * 6 col-blocks), y = 32 row-blocks.
// ---------------------------------------------------------------------------
__global__ __launch_bounds__(256) void proj_kernel(
    const float* __restrict__ X,
    const float* __restrict__ W0, const float* __restrict__ W1,
    const float* __restrict__ W2, const float* __restrict__ W3,
    const float* __restrict__ W4)
{
    __shared__ float As[8][128];
    __shared__ float Bs[8][128];

    const int bx      = blockIdx.x;
    const int which   = bx / 6;
    const int colBase = (bx % 6) * 128;     // within [0,768)
    const int rowBase = blockIdx.y * 128;   // within [0,4096)
    const float* W = (which == 0) ? W0 : (which == 1) ? W1 :
                     (which == 2) ? W2 : (which == 3) ? W3 : W4;

    const int tid = threadIdx.x;
    const int tx  = tid & 15;
    const int ty  = tid >> 4;
    const int lr  = tid >> 1;          // 0..127
    const int lk  = (tid & 1) * 4;     // 0 or 4

    const float* Ag = X + (size_t)(rowBase + lr) * DIM + lk;
    const float* Bg = W + (size_t)(colBase + lr) * DIM + lk;

    float acc[8][8];
    #pragma unroll
    for (int i = 0; i < 8; i++)
        #pragma unroll
        for (int j = 0; j < 8; j++) acc[i][j] = 0.f;

    for (int k0 = 0; k0 < DIM; k0 += 8) {
        float4 a = *(const float4*)(Ag + k0);
        float4 b = *(const float4*)(Bg + k0);
        As[lk+0][lr] = a.x; As[lk+1][lr] = a.y; As[lk+2][lr] = a.z; As[lk+3][lr] = a.w;
        Bs[lk+0][lr] = b.x; Bs[lk+1][lr] = b.y; Bs[lk+2][lr] = b.z; Bs[lk+3][lr] = b.w;
        __syncthreads();
        #pragma unroll
        for (int k = 0; k < 8; k++) {
            float ar[8], br[8];
            #pragma unroll
            for (int i = 0; i < 4; i++) {
                ar[i]   = As[k][ty*4 + i];
                ar[4+i] = As[k][64 + ty*4 + i];
            }
            #pragma unroll
            for (int j = 0; j < 4; j++) {
                br[j]   = Bs[k][tx*4 + j];
                br[4+j] = Bs[k][64 + tx*4 + j];
            }
            #pragma unroll
            for (int i = 0; i < 8; i++)
                #pragma unroll
                for (int j = 0; j < 8; j++)
                    acc[i][j] = fmaf(ar[i], br[j], acc[i][j]);
        }
        __syncthreads();
    }

    // Write into [which][b*H+h][s][d] layout
    #pragma unroll
    for (int i = 0; i < 8; i++) {
        int r  = rowBase + ty*4 + (i & 3) + ((i >= 4) ? 64 : 0);
        int b_ = r >> 11;            // /2048
        int s_ = r & (SQ - 1);
        #pragma unroll
        for (int j = 0; j < 8; j++) {
            int oo = colBase + tx*4 + (j & 3) + ((j >= 4) ? 64 : 0);
            int h  = oo >> 6;
            int d  = oo & 63;
            g_proj[(((size_t)which * BH + (b_ * NH + h)) * SQ + s_) * DH + d] = acc[i][j];
        }
    }
}

// ---------------------------------------------------------------------------
// Kernel 2: fused complex attention (flash-style online softmax).
// CTA = (64 q-rows) x (one bh).  256 threads as 16x16, 4x4 accum per thread.
// Score columns per thread: tx + 16*j (conflict-free kr/ki fragment loads).
// Output d-columns per thread: tx*4 + j (conflict-free v loads, vector store).
// ---------------------------------------------------------------------------
#define PAD 68

__global__ __launch_bounds__(256) void attn_kernel(float* __restrict__ out)
{
    extern __shared__ float sm[];
    float* qr_s = sm;
    float* qi_s = qr_s + 64*PAD;
    float* kr_s = qi_s + 64*PAD;
    float* ki_s = kr_s + 64*PAD;
    float* v_s  = ki_s + 64*PAD;
    float* p_s  = v_s  + 64*PAD;

    const int tid = threadIdx.x;
    const int tx  = tid & 15;
    const int ty  = tid >> 4;
    const int bh  = blockIdx.y;
    const int q0  = blockIdx.x * 64;

    const float* Qr = g_proj + ((size_t)(0*BH + bh) * SQ + q0) * DH;
    const float* Qi = g_proj + ((size_t)(1*BH + bh) * SQ + q0) * DH;

    // Load Q tiles (contiguous 4096 floats each)
    #pragma unroll
    for (int t = 0; t < 4; t++) {
        int idx = tid + t*256;
        int r = idx >> 4;
        int c = (idx & 15) << 2;
        *(float4*)&qr_s[r*PAD + c] = *(const float4*)&Qr[idx*4];
        *(float4*)&qi_s[r*PAD + c] = *(const float4*)&Qi[idx*4];
    }

    float o[16];
    float m[4], l[4];
    #pragma unroll
    for (int i = 0; i < 16; i++) o[i] = 0.f;
    #pragma unroll
    for (int i = 0; i < 4; i++) { m[i] = -1e30f; l[i] = 0.f; }

    const float scale = 0.125f;  // 1/sqrt(64)

    for (int kt = 0; kt < SQ/64; kt++) {
        const float* Kr = g_proj + ((size_t)(2*BH + bh) * SQ + kt*64) * DH;
        const float* Ki = g_proj + ((size_t)(3*BH + bh) * SQ + kt*64) * DH;
        const float* Vv = g_proj + ((size_t)(4*BH + bh) * SQ + kt*64) * DH;
        #pragma unroll
        for (int t = 0; t < 4; t++) {
            int idx = tid + t*256;
            int r = idx >> 4;
            int c = (idx & 15) << 2;
            *(float4*)&kr_s[r*PAD + c] = *(const float4*)&Kr[idx*4];
            *(float4*)&ki_s[r*PAD + c] = *(const float4*)&Ki[idx*4];
            *(float4*)&v_s [r*PAD + c] = *(const float4*)&Vv[idx*4];
        }
        __syncthreads();

        // --- scores: sr = qr.kr + qi.ki ; si = qi.kr - qr.ki ---
        float sr[16], si[16];
        #pragma unroll
        for (int i = 0; i < 16; i++) { sr[i] = 0.f; si[i] = 0.f; }

        #pragma unroll 4
        for (int d0 = 0; d0 < 64; d0 += 4) {
            float4 qrF[4], qiF[4], krF[4], kiF[4];
            #pragma unroll
            for (int i = 0; i < 4; i++) {
                qrF[i] = *(const float4*)&qr_s[(ty*4 + i)*PAD + d0];
                qiF[i] = *(const float4*)&qi_s[(ty*4 + i)*PAD + d0];
            }
            #pragma unroll
            for (int j = 0; j < 4; j++) {
                krF[j] = *(const float4*)&kr_s[(tx + 16*j)*PAD + d0];
                kiF[j] = *(const float4*)&ki_s[(tx + 16*j)*PAD + d0];
            }
            #pragma unroll
            for (int i = 0; i < 4; i++) {
                #pragma unroll
                for (int j = 0; j < 4; j++) {
#define CFMA(C) \
    sr[i*4+j] = fmaf( qrF[i].C, krF[j].C, sr[i*4+j]); \
    sr[i*4+j] = fmaf( qiF[i].C, kiF[j].C, sr[i*4+j]); \
    si[i*4+j] = fmaf( qiF[i].C, krF[j].C, si[i*4+j]); \
    si[i*4+j] = fmaf(-qrF[i].C, kiF[j].C, si[i*4+j]);
                    CFMA(x) CFMA(y) CFMA(z) CFMA(w)
#undef CFMA
                }
            }
        }

        // --- magnitude + online softmax per row ---
        #pragma unroll
        for (int i = 0; i < 4; i++) {
            float s0 = sqrtf(fmaf(sr[i*4+0], sr[i*4+0], si[i*4+0]*si[i*4+0])) * scale;
            float s1 = sqrtf(fmaf(sr[i*4+1], sr[i*4+1], si[i*4+1]*si[i*4+1])) * scale;
            float s2 = sqrtf(fmaf(sr[i*4+2], sr[i*4+2], si[i*4+2]*si[i*4+2])) * scale;
            float s3 = sqrtf(fmaf(sr[i*4+3], sr[i*4+3], si[i*4+3]*si[i*4+3])) * scale;
            float mx = fmaxf(fmaxf(s0, s1), fmaxf(s2, s3));
            #pragma unroll
            for (int off = 8; off >= 1; off >>= 1)
                mx = fmaxf(mx, __shfl_xor_sync(0xffffffffu, mx, off));
            float mnew = fmaxf(m[i], mx);
            float corr = __expf(m[i] - mnew);
            float p0 = __expf(s0 - mnew);
            float p1 = __expf(s1 - mnew);
            float p2 = __expf(s2 - mnew);
            float p3 = __expf(s3 - mnew);
            float* pr = &p_s[(ty*4 + i)*PAD];
            pr[tx] = p0; pr[tx+16] = p1; pr[tx+32] = p2; pr[tx+48] = p3;
            float rs = (p0 + p1) + (p2 + p3);
            #pragma unroll
            for (int off = 8; off >= 1; off >>= 1)
                rs += __shfl_xor_sync(0xffffffffu, rs, off);
            l[i] = l[i]*corr + rs;
            m[i] = mnew;
            o[i*4+0] *= corr; o[i*4+1] *= corr; o[i*4+2] *= corr; o[i*4+3] *= corr;
        }
        __syncthreads();

        // --- O += P @ V ---
        #pragma unroll 4
        for (int k0 = 0; k0 < 64; k0 += 4) {
            float4 pF[4], vF[4];
            #pragma unroll
            for (int i = 0; i < 4; i++)
                pF[i] = *(const float4*)&p_s[(ty*4 + i)*PAD + k0];
            #pragma unroll
            for (int kk = 0; kk < 4; kk++)
                vF[kk] = *(const float4*)&v_s[(k0 + kk)*PAD + tx*4];
            #pragma unroll
            for (int i = 0; i < 4; i++) {
#define PVS(C, jj) \
    o[i*4+jj] = fmaf(pF[i].x, vF[0].C, o[i*4+jj]); \
    o[i*4+jj] = fmaf(pF[i].y, vF[1].C, o[i*4+jj]); \
    o[i*4+jj] = fmaf(pF[i].z, vF[2].C, o[i*4+jj]); \
    o[i*4+jj] = fmaf(pF[i].w, vF[3].C, o[i*4+jj]);
                PVS(x,0) PVS(y,1) PVS(z,2) PVS(w,3)
#undef PVS
            }
        }
        __syncthreads();
    }

    // Epilogue: normalize and write [b, s, h*64+d]
    const int b_ = bh / NH, h = bh % NH;
    #pragma unroll
    for (int i = 0; i < 4; i++) {
        float inv = 1.0f / l[i];
        int row = q0 + ty*4 + i;
        float4 r4 = make_float4(o[i*4+0]*inv, o[i*4+1]*inv, o[i*4+2]*inv, o[i*4+3]*inv);
        *(float4*)&out[((size_t)(b_*SQ + row))*DIM + h*DH + tx*4] = r4;
    }
}

// ---------------------------------------------------------------------------
extern "C" void kernel_launch(void* const* d_in, const int* in_sizes, int n_in,
                              void* d_out, int out_size)
{
    const float* X   = (const float*)d_in[0];
    const float* Wqr = (const float*)d_in[1];
    const float* Wqi = (const float*)d_in[2];
    const float* Wkr = (const float*)d_in[3];
    const float* Wki = (const float*)d_in[4];
    const float* Wv  = (const float*)d_in[5];
    float* out = (float*)d_out;

    const int attn_smem = 6 * 64 * PAD * sizeof(float);  // 104448 B
    cudaFuncSetAttribute(attn_kernel, cudaFuncAttributeMaxDynamicSharedMemorySize, attn_smem);

    proj_kernel<<<dim3(30, 32), 256>>>(X, Wqr, Wqi, Wkr, Wki, Wv);
    attn_kernel<<<dim3(SQ/64, BH), 256, attn_smem>>>(out);
}

// round 6
// speedup vs baseline: 2.0560x; 2.0515x over previous
#include <cuda_runtime.h>
#include <cuda_fp16.h>
#include <cstdint>

// Problem constants
#define SQ   2048
#define DIM  768
#define NH   12
#define DH   64
#define NB   2
#define BH   (NB*NH)   // 24

// fp16 hi/lo scratch: [5][BH][S][DH]  (qr,qi,kr,ki,v)
__device__ __align__(16) __half g_hi[5u * BH * SQ * DH];
__device__ __align__(16) __half g_lo[5u * BH * SQ * DH];

// ---------------------------------------------------------------------------
// Kernel 1: fused projections (fp32 SIMT), epilogue emits fp16 hi/lo pairs.
// ---------------------------------------------------------------------------
__global__ __launch_bounds__(256) void proj_kernel(
    const float* __restrict__ X,
    const float* __restrict__ W0, const float* __restrict__ W1,
    const float* __restrict__ W2, const float* __restrict__ W3,
    const float* __restrict__ W4)
{
    __shared__ float As[8][128];
    __shared__ float Bs[8][128];

    const int bx      = blockIdx.x;
    const int which   = bx / 6;
    const int colBase = (bx % 6) * 128;
    const int rowBase = blockIdx.y * 128;
    const float* W = (which == 0) ? W0 : (which == 1) ? W1 :
                     (which == 2) ? W2 : (which == 3) ? W3 : W4;

    const int tid = threadIdx.x;
    const int tx  = tid & 15;
    const int ty  = tid >> 4;
    const int lr  = tid >> 1;
    const int lk  = (tid & 1) * 4;

    const float* Ag = X + (size_t)(rowBase + lr) * DIM + lk;
    const float* Bg = W + (size_t)(colBase + lr) * DIM + lk;

    float acc[8][8];
    #pragma unroll
    for (int i = 0; i < 8; i++)
        #pragma unroll
        for (int j = 0; j < 8; j++) acc[i][j] = 0.f;

    for (int k0 = 0; k0 < DIM; k0 += 8) {
        float4 a = *(const float4*)(Ag + k0);
        float4 b = *(const float4*)(Bg + k0);
        As[lk+0][lr] = a.x; As[lk+1][lr] = a.y; As[lk+2][lr] = a.z; As[lk+3][lr] = a.w;
        Bs[lk+0][lr] = b.x; Bs[lk+1][lr] = b.y; Bs[lk+2][lr] = b.z; Bs[lk+3][lr] = b.w;
        __syncthreads();
        #pragma unroll
        for (int k = 0; k < 8; k++) {
            float ar[8], br[8];
            #pragma unroll
            for (int i = 0; i < 4; i++) {
                ar[i]   = As[k][ty*4 + i];
                ar[4+i] = As[k][64 + ty*4 + i];
            }
            #pragma unroll
            for (int j = 0; j < 4; j++) {
                br[j]   = Bs[k][tx*4 + j];
                br[4+j] = Bs[k][64 + tx*4 + j];
            }
            #pragma unroll
            for (int i = 0; i < 8; i++)
                #pragma unroll
                for (int j = 0; j < 8; j++)
                    acc[i][j] = fmaf(ar[i], br[j], acc[i][j]);
        }
        __syncthreads();
    }

    #pragma unroll
    for (int i = 0; i < 8; i++) {
        int r  = rowBase + ty*4 + (i & 3) + ((i >= 4) ? 64 : 0);
        int b_ = r >> 11;
        int s_ = r & (SQ - 1);
        #pragma unroll
        for (int j = 0; j < 8; j++) {
            int oo = colBase + tx*4 + (j & 3) + ((j >= 4) ? 64 : 0);
            int h  = oo >> 6;
            int d  = oo & 63;
            size_t off = (((size_t)which * BH + (b_ * NH + h)) * SQ + s_) * DH + d;
            float v = acc[i][j];
            __half hh = __float2half_rn(v);
            g_hi[off] = hh;
            g_lo[off] = __float2half_rn(v - __half2float(hh));
        }
    }
}

// ---------------------------------------------------------------------------
// MMA helpers (legacy m16n8k16 f16 -> f32)
// ---------------------------------------------------------------------------
__device__ __forceinline__ uint32_t sm_u32(const void* p) {
    return (uint32_t)__cvta_generic_to_shared(p);
}
__device__ __forceinline__ void ldsm4(uint32_t* r, uint32_t a) {
    asm volatile("ldmatrix.sync.aligned.m8n8.x4.shared.b16 {%0,%1,%2,%3}, [%4];"
                 : "=r"(r[0]), "=r"(r[1]), "=r"(r[2]), "=r"(r[3]) : "r"(a));
}
__device__ __forceinline__ void ldsm4t(uint32_t* r, uint32_t a) {
    asm volatile("ldmatrix.sync.aligned.m8n8.x4.trans.shared.b16 {%0,%1,%2,%3}, [%4];"
                 : "=r"(r[0]), "=r"(r[1]), "=r"(r[2]), "=r"(r[3]) : "r"(a));
}
__device__ __forceinline__ void mma16816(float* c, const uint32_t* a,
                                         uint32_t b0, uint32_t b1) {
    asm volatile(
        "mma.sync.aligned.m16n8k16.row.col.f32.f16.f16.f32 "
        "{%0,%1,%2,%3},{%4,%5,%6,%7},{%8,%9},{%0,%1,%2,%3};"
        : "+f"(c[0]), "+f"(c[1]), "+f"(c[2]), "+f"(c[3])
        : "r"(a[0]), "r"(a[1]), "r"(a[2]), "r"(a[3]), "r"(b0), "r"(b1));
}

// ---------------------------------------------------------------------------
// Kernel 2: tensor-core complex flash attention.
// CTA = 128 q-rows x one bh, 8 warps (16 rows each). Q a-frags live in regs.
// Hi/lo fp16 split (3-segment Markidis) => fp32-grade accuracy.
// ---------------------------------------------------------------------------
#define KPAD 72   // smem row stride in halves (144B) -> conflict-free ldmatrix

__global__ __launch_bounds__(256, 1) void attn_kernel(float* __restrict__ out)
{
    extern __shared__ __half smh[];
    __half* qs = smh;                       // 4 * 128 * KPAD (qr_hi,qi_hi,qr_lo,qi_lo)
    __half* ks = smh + 4*128*KPAD;          // 4 * 64 * KPAD  (kr_hi,ki_hi,kr_lo,ki_lo)
    __half* vs = ks  + 4*64*KPAD;           // 2 * 64 * KPAD  (v_hi, v_lo)

    const int tid  = threadIdx.x;
    const int lane = tid & 31;
    const int w    = tid >> 5;
    const int bh   = blockIdx.y;
    const int q0   = blockIdx.x * 128;

    // --- stage Q tiles (coalesced uint4), then build A-frags in registers ---
    {
        const uint4* src[4] = {
            (const uint4*)(g_hi + ((size_t)(0*BH + bh) * SQ + q0) * DH),
            (const uint4*)(g_hi + ((size_t)(1*BH + bh) * SQ + q0) * DH),
            (const uint4*)(g_lo + ((size_t)(0*BH + bh) * SQ + q0) * DH),
            (const uint4*)(g_lo + ((size_t)(1*BH + bh) * SQ + q0) * DH)};
        #pragma unroll
        for (int it = 0; it < 16; it++) {
            int idx = tid + it*256;
            int arr = idx >> 10;
            int rem = idx & 1023;
            int row = rem >> 3;
            int c8  = rem & 7;
            *(uint4*)(qs + arr*128*KPAD + row*KPAD + c8*8) = src[arr][row*8 + c8];
        }
    }
    __syncthreads();

    uint32_t a_qr[2][4][4], a_qi[2][4][4];   // [hi/lo][k16 chunk][reg]
    {
        int r = lane & 15, sg = lane >> 4;
        #pragma unroll
        for (int hl = 0; hl < 2; hl++)
            #pragma unroll
            for (int c = 0; c < 4; c++) {
                ldsm4(a_qr[hl][c], sm_u32(qs + (hl*2+0)*128*KPAD + (w*16 + r)*KPAD + c*16 + sg*8));
                ldsm4(a_qi[hl][c], sm_u32(qs + (hl*2+1)*128*KPAD + (w*16 + r)*KPAD + c*16 + sg*8));
            }
    }

    float o_acc[8][4];
    #pragma unroll
    for (int t = 0; t < 8; t++)
        #pragma unroll
        for (int j = 0; j < 4; j++) o_acc[t][j] = 0.f;
    float m_[2] = {-1e30f, -1e30f};
    float l_[2] = {0.f, 0.f};

    const uint4* ksrc[6] = {
        (const uint4*)(g_hi + (size_t)(2*BH + bh) * SQ * DH),
        (const uint4*)(g_hi + (size_t)(3*BH + bh) * SQ * DH),
        (const uint4*)(g_lo + (size_t)(2*BH + bh) * SQ * DH),
        (const uint4*)(g_lo + (size_t)(3*BH + bh) * SQ * DH),
        (const uint4*)(g_hi + (size_t)(4*BH + bh) * SQ * DH),
        (const uint4*)(g_lo + (size_t)(4*BH + bh) * SQ * DH)};

    for (int kt = 0; kt < SQ/64; kt++) {
        // --- load K/V tiles (6 arrays of 64x64 halves) ---
        #pragma unroll
        for (int it = 0; it < 12; it++) {
            int idx = tid + it*256;
            int arr = idx >> 9;
            int rem = idx & 511;
            int row = rem >> 3;
            int c8  = rem & 7;
            __half* dst = (arr < 4) ? (ks + arr*64*KPAD) : (vs + (arr-4)*64*KPAD);
            *(uint4*)(dst + row*KPAD + c8*8) = ksrc[arr][(size_t)(kt*64 + row)*8 + c8];
        }
        __syncthreads();

        // --- scores: sr = qr.kr + qi.ki ; si = qi.kr - qr.ki (3 hi/lo segments) ---
        float sr[8][4], si[8][4];
        #pragma unroll
        for (int t = 0; t < 8; t++)
            #pragma unroll
            for (int j = 0; j < 4; j++) { sr[t][j] = 0.f; si[t][j] = 0.f; }

        const int q8 = lane >> 3, rr = lane & 7;
        #pragma unroll
        for (int seg = 0; seg < 3; seg++) {
            const int sa = (seg == 2) ? 1 : 0;   // A from lo on seg2
            const int sb = (seg == 1) ? 1 : 0;   // B from lo on seg1
            const __half* krp = ks + (sb*2 + 0)*64*KPAD;
            const __half* kip = ks + (sb*2 + 1)*64*KPAD;
            #pragma unroll
            for (int c = 0; c < 4; c++) {
                #pragma unroll
                for (int tp = 0; tp < 4; tp++) {
                    int row = tp*16 + (q8 >> 1)*8 + rr;
                    int col = c*16 + (q8 & 1)*8;
                    uint32_t br[4], bi[4];
                    ldsm4(br, sm_u32(krp + row*KPAD + col));
                    ldsm4(bi, sm_u32(kip + row*KPAD + col));
                    #pragma unroll
                    for (int tt = 0; tt < 2; tt++) {
                        int t = tp*2 + tt;
                        mma16816(sr[t], a_qr[sa][c], br[2*tt], br[2*tt+1]);
                        mma16816(sr[t], a_qi[sa][c], bi[2*tt], bi[2*tt+1]);
                        mma16816(si[t], a_qi[sa][c], br[2*tt], br[2*tt+1]);
                        mma16816(si[t], a_qr[sa][c],
                                 bi[2*tt] ^ 0x80008000u, bi[2*tt+1] ^ 0x80008000u);
                    }
                }
            }
        }

        // --- magnitude + online softmax (per thread: row-halves h=0,1) ---
        float pv_[2][16];
        #pragma unroll
        for (int h = 0; h < 2; h++) {
            float sv[16];
            float mx = m_[h];
            #pragma unroll
            for (int t = 0; t < 8; t++)
                #pragma unroll
                for (int j = 0; j < 2; j++) {
                    float a = sr[t][2*h + j], b = si[t][2*h + j];
                    float s = sqrtf(fmaf(a, a, b*b)) * 0.125f;
                    sv[t*2 + j] = s;
                    mx = fmaxf(mx, s);
                }
            mx = fmaxf(mx, __shfl_xor_sync(0xffffffffu, mx, 1));
            mx = fmaxf(mx, __shfl_xor_sync(0xffffffffu, mx, 2));
            float corr = __expf(m_[h] - mx);
            float sum = 0.f;
            #pragma unroll
            for (int kk = 0; kk < 16; kk++) {
                float p = __expf(sv[kk] - mx);
                pv_[h][kk] = p;
                sum += p;
            }
            sum += __shfl_xor_sync(0xffffffffu, sum, 1);
            sum += __shfl_xor_sync(0xffffffffu, sum, 2);
            l_[h] = l_[h]*corr + sum;
            m_[h] = mx;
            #pragma unroll
            for (int t = 0; t < 8; t++) {
                o_acc[t][2*h]   *= corr;
                o_acc[t][2*h+1] *= corr;
            }
        }

        // --- P -> fp16 hi/lo A-frags (C-frag of S == A-frag of PV) ---
        uint32_t pah[4][4], pal[4][4];
        #pragma unroll
        for (int c = 0; c < 4; c++)
            #pragma unroll
            for (int tt = 0; tt < 2; tt++)
                #pragma unroll
                for (int h = 0; h < 2; h++) {
                    int t = 2*c + tt;
                    float p0 = pv_[h][2*t], p1 = pv_[h][2*t + 1];
                    __half2 hh = __floats2half2_rn(p0, p1);
                    pah[c][tt*2 + h] = *reinterpret_cast<uint32_t*>(&hh);
                    __half2 ll = __floats2half2_rn(p0 - __low2float(hh),
                                                   p1 - __high2float(hh));
                    pal[c][tt*2 + h] = *reinterpret_cast<uint32_t*>(&ll);
                }

        // --- O += P @ V (3 hi/lo segments, V b-frags via ldmatrix.trans) ---
        #pragma unroll
        for (int seg = 0; seg < 3; seg++) {
            const uint32_t (*pa)[4] = (seg == 2) ? pal : pah;
            const __half* vp = vs + ((seg == 1) ? 1 : 0)*64*KPAD;
            #pragma unroll
            for (int c = 0; c < 4; c++) {
                #pragma unroll
                for (int tp = 0; tp < 4; tp++) {
                    int row = c*16 + (q8 & 1)*8 + rr;
                    int col = tp*16 + (q8 >> 1)*8;
                    uint32_t bv[4];
                    ldsm4t(bv, sm_u32(vp + row*KPAD + col));
                    mma16816(o_acc[2*tp],     pa[c], bv[0], bv[1]);
                    mma16816(o_acc[2*tp + 1], pa[c], bv[2], bv[3]);
                }
            }
        }
        __syncthreads();
    }

    // --- epilogue: normalize, write out[b][s][h*64+d] ---
    const int b_ = bh / NH, hd = bh % NH;
    const int g  = lane >> 2, nj = (lane & 3)*2;
    #pragma unroll
    for (int h = 0; h < 2; h++) {
        float inv = 1.0f / l_[h];
        int row = q0 + w*16 + g + h*8;
        float* orow = out + (size_t)(b_*SQ + row)*DIM + hd*DH;
        #pragma unroll
        for (int t = 0; t < 8; t++) {
            float2 v2 = make_float2(o_acc[t][2*h]*inv, o_acc[t][2*h+1]*inv);
            *(float2*)(orow + t*8 + nj) = v2;
        }
    }
}

// ---------------------------------------------------------------------------
extern "C" void kernel_launch(void* const* d_in, const int* in_sizes, int n_in,
                              void* d_out, int out_size)
{
    const float* X   = (const float*)d_in[0];
    const float* Wqr = (const float*)d_in[1];
    const float* Wqi = (const float*)d_in[2];
    const float* Wkr = (const float*)d_in[3];
    const float* Wki = (const float*)d_in[4];
    const float* Wv  = (const float*)d_in[5];
    float* out = (float*)d_out;

    const int attn_smem = (4*128 + 4*64 + 2*64) * KPAD * (int)sizeof(__half); // 129024
    cudaFuncSetAttribute(attn_kernel, cudaFuncAttributeMaxDynamicSharedMemorySize, attn_smem);

    proj_kernel<<<dim3(30, 32), 256>>>(X, Wqr, Wqi, Wkr, Wki, Wv);
    attn_kernel<<<dim3(SQ/128, BH), 256, attn_smem>>>(out);
}

// round 7
// speedup vs baseline: 3.5536x; 1.7284x over previous
#include <cuda_runtime.h>
#include <cuda_fp16.h>
#include <cstdint>

// Problem constants
#define SQ   2048
#define DIM  768
#define NH   12
#define DH   64
#define NB   2
#define BH   (NB*NH)   // 24

// fp16 hi/lo scratch: [5][BH][S][DH]  (qr,qi,kr,ki,v)
__device__ __align__(16) __half g_hi[5u * BH * SQ * DH];
__device__ __align__(16) __half g_lo[5u * BH * SQ * DH];
// fp16 hi/lo copies of inputs
__device__ __align__(16) __half g_xhi[4096u * DIM], g_xlo[4096u * DIM];
__device__ __align__(16) __half g_whi[5u * DIM * DIM], g_wlo[5u * DIM * DIM];

// ---------------------------------------------------------------------------
// helpers
// ---------------------------------------------------------------------------
__device__ __forceinline__ uint32_t sm_u32(const void* p) {
    return (uint32_t)__cvta_generic_to_shared(p);
}
__device__ __forceinline__ void ldsm4(uint32_t* r, uint32_t a) {
    asm volatile("ldmatrix.sync.aligned.m8n8.x4.shared.b16 {%0,%1,%2,%3}, [%4];"
                 : "=r"(r[0]), "=r"(r[1]), "=r"(r[2]), "=r"(r[3]) : "r"(a));
}
__device__ __forceinline__ void ldsm4t(uint32_t* r, uint32_t a) {
    asm volatile("ldmatrix.sync.aligned.m8n8.x4.trans.shared.b16 {%0,%1,%2,%3}, [%4];"
                 : "=r"(r[0]), "=r"(r[1]), "=r"(r[2]), "=r"(r[3]) : "r"(a));
}
__device__ __forceinline__ void mma16816(float* c, const uint32_t* a,
                                         uint32_t b0, uint32_t b1) {
    asm volatile(
        "mma.sync.aligned.m16n8k16.row.col.f32.f16.f16.f32 "
        "{%0,%1,%2,%3},{%4,%5,%6,%7},{%8,%9},{%0,%1,%2,%3};"
        : "+f"(c[0]), "+f"(c[1]), "+f"(c[2]), "+f"(c[3])
        : "r"(a[0]), "r"(a[1]), "r"(a[2]), "r"(a[3]), "r"(b0), "r"(b1));
}
__device__ __forceinline__ void cpa16(uint32_t d, const void* s) {
    asm volatile("cp.async.cg.shared.global [%0], [%1], 16;" :: "r"(d), "l"(s));
}
__device__ __forceinline__ void cp_commit() { asm volatile("cp.async.commit_group;"); }
template<int N> __device__ __forceinline__ void cp_wait() {
    asm volatile("cp.async.wait_group %0;" :: "n"(N));
}

// ---------------------------------------------------------------------------
// Kernel 0: split fp32 inputs into fp16 hi/lo (HBM-bound, ~15us)
// ---------------------------------------------------------------------------
__global__ __launch_bounds__(256) void split_kernel(
    const float* __restrict__ X,
    const float* __restrict__ W0, const float* __restrict__ W1,
    const float* __restrict__ W2, const float* __restrict__ W3,
    const float* __restrict__ W4)
{
    const int64_t NX4 = (int64_t)4096 * DIM / 4;
    const int64_t NW4 = (int64_t)DIM * DIM / 4;
    const int64_t total4 = NX4 + 5 * NW4;
    for (int64_t i4 = (int64_t)blockIdx.x * 256 + threadIdx.x;
         i4 < total4; i4 += (int64_t)gridDim.x * 256) {
        float4 v;
        __half2* dh; __half2* dl;
        if (i4 < NX4) {
            v = ((const float4*)X)[i4];
            dh = (__half2*)g_xhi + i4*2; dl = (__half2*)g_xlo + i4*2;
        } else {
            int64_t j = i4 - NX4;
            int ws = (int)(j / NW4);
            int64_t rem = j - (int64_t)ws * NW4;
            const float* Wp = (ws == 0) ? W0 : (ws == 1) ? W1 :
                              (ws == 2) ? W2 : (ws == 3) ? W3 : W4;
            v = ((const float4*)Wp)[rem];
            dh = (__half2*)g_whi + i4*2 - NX4*2;
            dl = (__half2*)g_wlo + i4*2 - NX4*2;
        }
        __half hx = __float2half_rn(v.x), hy = __float2half_rn(v.y);
        __half hz = __float2half_rn(v.z), hw = __float2half_rn(v.w);
        dh[0] = __halves2half2(hx, hy);
        dh[1] = __halves2half2(hz, hw);
        dl[0] = __halves2half2(__float2half_rn(v.x - __half2float(hx)),
                               __float2half_rn(v.y - __half2float(hy)));
        dl[1] = __halves2half2(__float2half_rn(v.z - __half2float(hz)),
                               __float2half_rn(v.w - __half2float(hw)));
    }
}

// ---------------------------------------------------------------------------
// Kernel 1: tensor-core projections.  C = X @ W^T, 3-segment hi/lo fp16 MMA.
// CTA 128x128, 8 warps (2x4), warp tile 64x32. cp.async double-buffered k64.
// ---------------------------------------------------------------------------
#define PKP  72
#define PSTG (4*128*PKP)   // halves per stage (Ahi,Alo,Bhi,Blo)

__global__ __launch_bounds__(256) void proj_mma_kernel()
{
    extern __shared__ __half sp[];
    const int tid  = threadIdx.x;
    const int lane = tid & 31;
    const int w    = tid >> 5;
    const int bx      = blockIdx.x;
    const int which   = bx / 6;
    const int colBase = (bx % 6) * 128;
    const int rowBase = blockIdx.y * 128;

    const __half* Ahi = g_xhi;
    const __half* Alo = g_xlo;
    const __half* Bhi = g_whi + (size_t)which * DIM * DIM;
    const __half* Blo = g_wlo + (size_t)which * DIM * DIM;

    auto load_stage = [&](int s, int k0) {
        #pragma unroll
        for (int it = 0; it < 16; it++) {
            int idx = tid + it*256;
            int arr = idx >> 10;
            int rem = idx & 1023;
            int row = rem >> 3;
            int c8  = (rem & 7) * 8;
            const __half* gsrc;
            if (arr == 0)      gsrc = Ahi + (size_t)(rowBase + row)*DIM + k0 + c8;
            else if (arr == 1) gsrc = Alo + (size_t)(rowBase + row)*DIM + k0 + c8;
            else if (arr == 2) gsrc = Bhi + (size_t)(colBase + row)*DIM + k0 + c8;
            else               gsrc = Blo + (size_t)(colBase + row)*DIM + k0 + c8;
            cpa16(sm_u32(sp + s*PSTG + arr*128*PKP + row*PKP + c8), gsrc);
        }
    };

    float acc[4][4][4];
    #pragma unroll
    for (int mt = 0; mt < 4; mt++)
        #pragma unroll
        for (int nt = 0; nt < 4; nt++)
            #pragma unroll
            for (int j = 0; j < 4; j++) acc[mt][nt][j] = 0.f;

    const int r  = lane & 15, sg = lane >> 4;
    const int q8 = lane >> 3, rr = lane & 7;
    const int wRow = (w >> 2) * 64;
    const int wCol = (w & 3) * 32;

    load_stage(0, 0); cp_commit();

    #pragma unroll 1
    for (int it = 0; it < 12; it++) {
        if (it + 1 < 12) { load_stage((it+1) & 1, (it+1)*64); cp_commit(); cp_wait<1>(); }
        else             cp_wait<0>();
        __syncthreads();

        const __half* A0 = sp + (it & 1)*PSTG;
        const __half* A1 = A0 + 128*PKP;
        const __half* B0 = A0 + 2*128*PKP;
        const __half* B1 = A0 + 3*128*PKP;

        #pragma unroll
        for (int kc = 0; kc < 4; kc++) {
            uint32_t ah[4][4], al[4][4], bh[2][4], bl[2][4];
            #pragma unroll
            for (int mt = 0; mt < 4; mt++) {
                ldsm4(ah[mt], sm_u32(A0 + (wRow + mt*16 + r)*PKP + kc*16 + sg*8));
                ldsm4(al[mt], sm_u32(A1 + (wRow + mt*16 + r)*PKP + kc*16 + sg*8));
            }
            #pragma unroll
            for (int np = 0; np < 2; np++) {
                int brow = (wCol + np*16 + (q8 >> 1)*8 + rr)*PKP + kc*16 + (q8 & 1)*8;
                ldsm4(bh[np], sm_u32(B0 + brow));
                ldsm4(bl[np], sm_u32(B1 + brow));
            }
            #pragma unroll
            for (int mt = 0; mt < 4; mt++)
                #pragma unroll
                for (int np = 0; np < 2; np++)
                    #pragma unroll
                    for (int tt = 0; tt < 2; tt++) {
                        float* c = acc[mt][np*2 + tt];
                        mma16816(c, ah[mt], bh[np][2*tt], bh[np][2*tt+1]);
                        mma16816(c, ah[mt], bl[np][2*tt], bl[np][2*tt+1]);
                        mma16816(c, al[mt], bh[np][2*tt], bh[np][2*tt+1]);
                    }
        }
        __syncthreads();
    }

    // epilogue: write per-head fp16 hi/lo scratch (half2 stores, d even)
    #pragma unroll
    for (int mt = 0; mt < 4; mt++)
        #pragma unroll
        for (int nt = 0; nt < 4; nt++)
            #pragma unroll
            for (int jh = 0; jh < 2; jh++) {
                int row = rowBase + wRow + mt*16 + (lane >> 2) + jh*8;
                int col = colBase + wCol + nt*8 + (lane & 3)*2;
                int b_ = row >> 11, s_ = row & (SQ - 1);
                int h  = col >> 6,  d  = col & 63;
                size_t off = (((size_t)which*BH + (b_*NH + h))*SQ + s_)*DH + d;
                float v0 = acc[mt][nt][jh*2 + 0];
                float v1 = acc[mt][nt][jh*2 + 1];
                __half h0 = __float2half_rn(v0), h1 = __float2half_rn(v1);
                *(__half2*)(g_hi + off) = __halves2half2(h0, h1);
                *(__half2*)(g_lo + off) = __halves2half2(
                    __float2half_rn(v0 - __half2float(h0)),
                    __float2half_rn(v1 - __half2float(h1)));
            }
}

// ---------------------------------------------------------------------------
// Kernel 2: tensor-core complex flash attention (2-segment hi/lo).
// CTA = 128 q-rows x one bh, 8 warps. Q hi A-frags live in registers.
// scores: (q_hi)·(k_hi) + (q_hi)·(k_lo);  PV: (p_hi)·(v_hi) + (p_hi)·(v_lo)
// ---------------------------------------------------------------------------
#define KPAD 72

__global__ __launch_bounds__(256, 1) void attn_kernel(float* __restrict__ out)
{
    extern __shared__ __half smh[];
    __half* qs = smh;                       // 2 * 128 * KPAD (qr_hi, qi_hi)
    __half* ks = smh + 2*128*KPAD;          // 4 * 64 * KPAD  (kr_hi,ki_hi,kr_lo,ki_lo)
    __half* vs = ks  + 4*64*KPAD;           // 2 * 64 * KPAD  (v_hi, v_lo)

    const int tid  = threadIdx.x;
    const int lane = tid & 31;
    const int w    = tid >> 5;
    const int bh   = blockIdx.y;
    const int q0   = blockIdx.x * 128;

    // stage Q hi tiles
    {
        const uint4* src[2] = {
            (const uint4*)(g_hi + ((size_t)(0*BH + bh) * SQ + q0) * DH),
            (const uint4*)(g_hi + ((size_t)(1*BH + bh) * SQ + q0) * DH)};
        #pragma unroll
        for (int it = 0; it < 8; it++) {
            int idx = tid + it*256;
            int arr = idx >> 10;
            int rem = idx & 1023;
            int row = rem >> 3;
            int c8  = rem & 7;
            *(uint4*)(qs + arr*128*KPAD + row*KPAD + c8*8) = src[arr][row*8 + c8];
        }
    }
    __syncthreads();

    uint32_t a_qr[4][4], a_qi[4][4];
    {
        int r = lane & 15, sg = lane >> 4;
        #pragma unroll
        for (int c = 0; c < 4; c++) {
            ldsm4(a_qr[c], sm_u32(qs + 0*128*KPAD + (w*16 + r)*KPAD + c*16 + sg*8));
            ldsm4(a_qi[c], sm_u32(qs + 1*128*KPAD + (w*16 + r)*KPAD + c*16 + sg*8));
        }
    }

    float o_acc[8][4];
    #pragma unroll
    for (int t = 0; t < 8; t++)
        #pragma unroll
        for (int j = 0; j < 4; j++) o_acc[t][j] = 0.f;
    float m_[2] = {-1e30f, -1e30f};
    float l_[2] = {0.f, 0.f};

    const uint4* ksrc[6] = {
        (const uint4*)(g_hi + (size_t)(2*BH + bh) * SQ * DH),
        (const uint4*)(g_hi + (size_t)(3*BH + bh) * SQ * DH),
        (const uint4*)(g_lo + (size_t)(2*BH + bh) * SQ * DH),
        (const uint4*)(g_lo + (size_t)(3*BH + bh) * SQ * DH),
        (const uint4*)(g_hi + (size_t)(4*BH + bh) * SQ * DH),
        (const uint4*)(g_lo + (size_t)(4*BH + bh) * SQ * DH)};

    for (int kt = 0; kt < SQ/64; kt++) {
        #pragma unroll
        for (int it = 0; it < 12; it++) {
            int idx = tid + it*256;
            int arr = idx >> 9;
            int rem = idx & 511;
            int row = rem >> 3;
            int c8  = rem & 7;
            __half* dst = (arr < 4) ? (ks + arr*64*KPAD) : (vs + (arr-4)*64*KPAD);
            *(uint4*)(dst + row*KPAD + c8*8) = ksrc[arr][(size_t)(kt*64 + row)*8 + c8];
        }
        __syncthreads();

        // scores (2 segments: B hi, B lo)
        float sr[8][4], si[8][4];
        #pragma unroll
        for (int t = 0; t < 8; t++)
            #pragma unroll
            for (int j = 0; j < 4; j++) { sr[t][j] = 0.f; si[t][j] = 0.f; }

        const int q8 = lane >> 3, rr = lane & 7;
        #pragma unroll
        for (int seg = 0; seg < 2; seg++) {
            const __half* krp = ks + (seg*2 + 0)*64*KPAD;
            const __half* kip = ks + (seg*2 + 1)*64*KPAD;
            #pragma unroll
            for (int c = 0; c < 4; c++) {
                #pragma unroll
                for (int tp = 0; tp < 4; tp++) {
                    int row = tp*16 + (q8 >> 1)*8 + rr;
                    int col = c*16 + (q8 & 1)*8;
                    uint32_t br[4], bi[4];
                    ldsm4(br, sm_u32(krp + row*KPAD + col));
                    ldsm4(bi, sm_u32(kip + row*KPAD + col));
                    #pragma unroll
                    for (int tt = 0; tt < 2; tt++) {
                        int t = tp*2 + tt;
                        mma16816(sr[t], a_qr[c], br[2*tt], br[2*tt+1]);
                        mma16816(sr[t], a_qi[c], bi[2*tt], bi[2*tt+1]);
                        mma16816(si[t], a_qi[c], br[2*tt], br[2*tt+1]);
                        mma16816(si[t], a_qr[c],
                                 bi[2*tt] ^ 0x80008000u, bi[2*tt+1] ^ 0x80008000u);
                    }
                }
            }
        }

        // magnitude + online softmax
        float pv_[2][16];
        #pragma unroll
        for (int h = 0; h < 2; h++) {
            float sv[16];
            float mx = m_[h];
            #pragma unroll
            for (int t = 0; t < 8; t++)
                #pragma unroll
                for (int j = 0; j < 2; j++) {
                    float a = sr[t][2*h + j], b = si[t][2*h + j];
                    float s = sqrtf(fmaf(a, a, b*b)) * 0.125f;
                    sv[t*2 + j] = s;
                    mx = fmaxf(mx, s);
                }
            mx = fmaxf(mx, __shfl_xor_sync(0xffffffffu, mx, 1));
            mx = fmaxf(mx, __shfl_xor_sync(0xffffffffu, mx, 2));
            float corr = __expf(m_[h] - mx);
            float sum = 0.f;
            #pragma unroll
            for (int kk = 0; kk < 16; kk++) {
                float p = __expf(sv[kk] - mx);
                pv_[h][kk] = p;
                sum += p;
            }
            sum += __shfl_xor_sync(0xffffffffu, sum, 1);
            sum += __shfl_xor_sync(0xffffffffu, sum, 2);
            l_[h] = l_[h]*corr + sum;
            m_[h] = mx;
            #pragma unroll
            for (int t = 0; t < 8; t++) {
                o_acc[t][2*h]   *= corr;
                o_acc[t][2*h+1] *= corr;
            }
        }

        // P -> fp16 hi A-frags (C-frag layout == A-frag layout)
        uint32_t pah[4][4];
        #pragma unroll
        for (int c = 0; c < 4; c++)
            #pragma unroll
            for (int tt = 0; tt < 2; tt++)
                #pragma unroll
                for (int h = 0; h < 2; h++) {
                    int t = 2*c + tt;
                    __half2 hh = __floats2half2_rn(pv_[h][2*t], pv_[h][2*t + 1]);
                    pah[c][tt*2 + h] = *reinterpret_cast<uint32_t*>(&hh);
                }

        // O += P @ V (2 segments: V hi, V lo)
        #pragma unroll
        for (int seg = 0; seg < 2; seg++) {
            const __half* vp = vs + seg*64*KPAD;
            #pragma unroll
            for (int c = 0; c < 4; c++) {
                #pragma unroll
                for (int tp = 0; tp < 4; tp++) {
                    int row = c*16 + (q8 & 1)*8 + rr;
                    int col = tp*16 + (q8 >> 1)*8;
                    uint32_t bv[4];
                    ldsm4t(bv, sm_u32(vp + row*KPAD + col));
                    mma16816(o_acc[2*tp],     pah[c], bv[0], bv[1]);
                    mma16816(o_acc[2*tp + 1], pah[c], bv[2], bv[3]);
                }
            }
        }
        __syncthreads();
    }

    // epilogue
    const int b_ = bh / NH, hd = bh % NH;
    const int g  = lane >> 2, nj = (lane & 3)*2;
    #pragma unroll
    for (int h = 0; h < 2; h++) {
        float inv = 1.0f / l_[h];
        int row = q0 + w*16 + g + h*8;
        float* orow = out + (size_t)(b_*SQ + row)*DIM + hd*DH;
        #pragma unroll
        for (int t = 0; t < 8; t++) {
            float2 v2 = make_float2(o_acc[t][2*h]*inv, o_acc[t][2*h+1]*inv);
            *(float2*)(orow + t*8 + nj) = v2;
        }
    }
}

// ---------------------------------------------------------------------------
extern "C" void kernel_launch(void* const* d_in, const int* in_sizes, int n_in,
                              void* d_out, int out_size)
{
    const float* X   = (const float*)d_in[0];
    const float* Wqr = (const float*)d_in[1];
    const float* Wqi = (const float*)d_in[2];
    const float* Wkr = (const float*)d_in[3];
    const float* Wki = (const float*)d_in[4];
    const float* Wv  = (const float*)d_in[5];
    float* out = (float*)d_out;

    const int proj_smem = 2 * PSTG * (int)sizeof(__half);                 // 147456
    const int attn_smem = (2*128 + 4*64 + 2*64) * KPAD * (int)sizeof(__half); // 92160
    cudaFuncSetAttribute(proj_mma_kernel, cudaFuncAttributeMaxDynamicSharedMemorySize, proj_smem);
    cudaFuncSetAttribute(attn_kernel, cudaFuncAttributeMaxDynamicSharedMemorySize, attn_smem);

    split_kernel<<<1024, 256>>>(X, Wqr, Wqi, Wkr, Wki, Wv);
    proj_mma_kernel<<<dim3(30, 32), 256, proj_smem>>>();
    attn_kernel<<<dim3(SQ/128, BH), 256, attn_smem>>>(out);
}

// round 9
// speedup vs baseline: 5.3657x; 1.5099x over previous
#include <cuda_runtime.h>
#include <cuda_fp16.h>
#include <cstdint>

// Problem constants
#define SQ   2048
#define DIM  768
#define NH   12
#define DH   64
#define NB   2
#define BH   (NB*NH)   // 24

// fp16 scratch: [5][BH][S][DH]  (qr,qi,kr,ki,v) — hi (rn-rounded) only
__device__ __align__(16) __half g_hi[5u * BH * SQ * DH];
// fp16 copies of inputs: X hi only; W hi+lo (weights keep full precision)
__device__ __align__(16) __half g_xhi[4096u * DIM];
__device__ __align__(16) __half g_whi[5u * DIM * DIM], g_wlo[5u * DIM * DIM];

// ---------------------------------------------------------------------------
// helpers
// ---------------------------------------------------------------------------
__device__ __forceinline__ uint32_t sm_u32(const void* p) {
    return (uint32_t)__cvta_generic_to_shared(p);
}
__device__ __forceinline__ void ldsm4(uint32_t* r, uint32_t a) {
    asm volatile("ldmatrix.sync.aligned.m8n8.x4.shared.b16 {%0,%1,%2,%3}, [%4];"
                 : "=r"(r[0]), "=r"(r[1]), "=r"(r[2]), "=r"(r[3]) : "r"(a));
}
__device__ __forceinline__ void ldsm4t(uint32_t* r, uint32_t a) {
    asm volatile("ldmatrix.sync.aligned.m8n8.x4.trans.shared.b16 {%0,%1,%2,%3}, [%4];"
                 : "=r"(r[0]), "=r"(r[1]), "=r"(r[2]), "=r"(r[3]) : "r"(a));
}
__device__ __forceinline__ void mma16816(float* c, const uint32_t* a,
                                         uint32_t b0, uint32_t b1) {
    asm volatile(
        "mma.sync.aligned.m16n8k16.row.col.f32.f16.f16.f32 "
        "{%0,%1,%2,%3},{%4,%5,%6,%7},{%8,%9},{%0,%1,%2,%3};"
        : "+f"(c[0]), "+f"(c[1]), "+f"(c[2]), "+f"(c[3])
        : "r"(a[0]), "r"(a[1]), "r"(a[2]), "r"(a[3]), "r"(b0), "r"(b1));
}
__device__ __forceinline__ void cpa16(uint32_t d, const void* s) {
    asm volatile("cp.async.cg.shared.global [%0], [%1], 16;" :: "r"(d), "l"(s));
}
__device__ __forceinline__ void cp_commit() { asm volatile("cp.async.commit_group;"); }
template<int N> __device__ __forceinline__ void cp_wait() {
    asm volatile("cp.async.wait_group %0;" :: "n"(N));
}

// ---------------------------------------------------------------------------
// Kernel 0: split fp32 inputs -> fp16 (X: hi; W: hi+lo)
// ---------------------------------------------------------------------------
__global__ __launch_bounds__(256) void split_kernel(
    const float* __restrict__ X,
    const float* __restrict__ W0, const float* __restrict__ W1,
    const float* __restrict__ W2, const float* __restrict__ W3,
    const float* __restrict__ W4)
{
    const int64_t NX4 = (int64_t)4096 * DIM / 4;
    const int64_t NW4 = (int64_t)DIM * DIM / 4;
    const int64_t total4 = NX4 + 5 * NW4;
    for (int64_t i4 = (int64_t)blockIdx.x * 256 + threadIdx.x;
         i4 < total4; i4 += (int64_t)gridDim.x * 256) {
        if (i4 < NX4) {
            float4 v = ((const float4*)X)[i4];
            __half2* dh = (__half2*)g_xhi + i4*2;
            dh[0] = __floats2half2_rn(v.x, v.y);
            dh[1] = __floats2half2_rn(v.z, v.w);
        } else {
            int64_t j = i4 - NX4;
            int ws = (int)(j / NW4);
            int64_t rem = j - (int64_t)ws * NW4;
            const float* Wp = (ws == 0) ? W0 : (ws == 1) ? W1 :
                              (ws == 2) ? W2 : (ws == 3) ? W3 : W4;
            float4 v = ((const float4*)Wp)[rem];
            __half2* dh = (__half2*)g_whi + j*2;
            __half2* dl = (__half2*)g_wlo + j*2;
            __half hx = __float2half_rn(v.x), hy = __float2half_rn(v.y);
            __half hz = __float2half_rn(v.z), hw = __float2half_rn(v.w);
            dh[0] = __halves2half2(hx, hy);
            dh[1] = __halves2half2(hz, hw);
            dl[0] = __halves2half2(__float2half_rn(v.x - __half2float(hx)),
                                   __float2half_rn(v.y - __half2float(hy)));
            dl[1] = __halves2half2(__float2half_rn(v.z - __half2float(hz)),
                                   __float2half_rn(v.w - __half2float(hw)));
        }
    }
}

// ---------------------------------------------------------------------------
// Kernel 1: tensor-core projections.  C = X @ W^T, 2-segment: Ahi*(Bhi+Blo).
// CTA 128x128, 8 warps (2x4), warp tile 64x32. cp.async double-buffered k64.
// ---------------------------------------------------------------------------
#define PKP  72
#define PSTG (3*128*PKP)   // halves per stage (Ahi,Bhi,Blo)

__global__ __launch_bounds__(256) void proj_mma_kernel()
{
    extern __shared__ __half sp[];
    const int tid  = threadIdx.x;
    const int lane = tid & 31;
    const int w    = tid >> 5;
    const int bx      = blockIdx.x;
    const int which   = bx / 6;
    const int colBase = (bx % 6) * 128;
    const int rowBase = blockIdx.y * 128;

    const __half* Ahi = g_xhi;
    const __half* Bhi = g_whi + (size_t)which * DIM * DIM;
    const __half* Blo = g_wlo + (size_t)which * DIM * DIM;

    auto load_stage = [&](int s, int k0) {
        #pragma unroll
        for (int it = 0; it < 12; it++) {
            int idx = tid + it*256;          // < 3072
            int arr = idx >> 10;             // 0..2
            int rem = idx & 1023;
            int row = rem >> 3;
            int c8  = (rem & 7) * 8;
            const __half* gsrc;
            if (arr == 0)      gsrc = Ahi + (size_t)(rowBase + row)*DIM + k0 + c8;
            else if (arr == 1) gsrc = Bhi + (size_t)(colBase + row)*DIM + k0 + c8;
            else               gsrc = Blo + (size_t)(colBase + row)*DIM + k0 + c8;
            cpa16(sm_u32(sp + s*PSTG + arr*128*PKP + row*PKP + c8), gsrc);
        }
    };

    float acc[4][4][4];
    #pragma unroll
    for (int mt = 0; mt < 4; mt++)
        #pragma unroll
        for (int nt = 0; nt < 4; nt++)
            #pragma unroll
            for (int j = 0; j < 4; j++) acc[mt][nt][j] = 0.f;

    const int r  = lane & 15, sg = lane >> 4;
    const int q8 = lane >> 3, rr = lane & 7;
    const int wRow = (w >> 2) * 64;
    const int wCol = (w & 3) * 32;

    load_stage(0, 0); cp_commit();

    #pragma unroll 1
    for (int it = 0; it < 12; it++) {
        if (it + 1 < 12) { load_stage((it+1) & 1, (it+1)*64); cp_commit(); cp_wait<1>(); }
        else             cp_wait<0>();
        __syncthreads();

        const __half* A0 = sp + (it & 1)*PSTG;
        const __half* B0 = A0 + 128*PKP;
        const __half* B1 = A0 + 2*128*PKP;

        #pragma unroll
        for (int kc = 0; kc < 4; kc++) {
            uint32_t ah[4][4], bh[2][4], bl[2][4];
            #pragma unroll
            for (int mt = 0; mt < 4; mt++)
                ldsm4(ah[mt], sm_u32(A0 + (wRow + mt*16 + r)*PKP + kc*16 + sg*8));
            #pragma unroll
            for (int np = 0; np < 2; np++) {
                int brow = (wCol + np*16 + (q8 >> 1)*8 + rr)*PKP + kc*16 + (q8 & 1)*8;
                ldsm4(bh[np], sm_u32(B0 + brow));
                ldsm4(bl[np], sm_u32(B1 + brow));
            }
            #pragma unroll
            for (int mt = 0; mt < 4; mt++)
                #pragma unroll
                for (int np = 0; np < 2; np++)
                    #pragma unroll
                    for (int tt = 0; tt < 2; tt++) {
                        float* c = acc[mt][np*2 + tt];
                        mma16816(c, ah[mt], bh[np][2*tt], bh[np][2*tt+1]);
                        mma16816(c, ah[mt], bl[np][2*tt], bl[np][2*tt+1]);
                    }
        }
        __syncthreads();
    }

    // epilogue: write per-head fp16 scratch (half2 stores, d even)
    #pragma unroll
    for (int mt = 0; mt < 4; mt++)
        #pragma unroll
        for (int nt = 0; nt < 4; nt++)
            #pragma unroll
            for (int jh = 0; jh < 2; jh++) {
                int row = rowBase + wRow + mt*16 + (lane >> 2) + jh*8;
                int col = colBase + wCol + nt*8 + (lane & 3)*2;
                int b_ = row >> 11, s_ = row & (SQ - 1);
                int h  = col >> 6,  d  = col & 63;
                size_t off = (((size_t)which*BH + (b_*NH + h))*SQ + s_)*DH + d;
                *(__half2*)(g_hi + off) =
                    __floats2half2_rn(acc[mt][nt][jh*2 + 0], acc[mt][nt][jh*2 + 1]);
            }
}

// ---------------------------------------------------------------------------
// Kernel 2: tensor-core complex flash attention (fp16, 1 segment).
// CTA = 128 q-rows x one bh, 8 warps. Q A-frags in registers.
// K/V tiles (kr,ki,v) cp.async double-buffered.
// ---------------------------------------------------------------------------
#define KPAD 72
#define KVSTG (3*64*KPAD)   // halves per KV stage

__global__ __launch_bounds__(256, 1) void attn_kernel(float* __restrict__ out)
{
    extern __shared__ __half smh[];
    __half* qs  = smh;                  // 2 * 128 * KPAD (qr, qi)
    __half* kvs = smh + 2*128*KPAD;     // 2 stages * (kr,ki,v) 64*KPAD each

    const int tid  = threadIdx.x;
    const int lane = tid & 31;
    const int w    = tid >> 5;
    const int bh   = blockIdx.y;
    const int q0   = blockIdx.x * 128;

    const __half* Kr = g_hi + (size_t)(2*BH + bh) * SQ * DH;
    const __half* Ki = g_hi + (size_t)(3*BH + bh) * SQ * DH;
    const __half* Vv = g_hi + (size_t)(4*BH + bh) * SQ * DH;

    auto load_kv = [&](int s, int kt) {
        #pragma unroll
        for (int it = 0; it < 6; it++) {
            int idx = tid + it*256;          // < 1536
            int arr = idx >> 9;              // 0..2
            int rem = idx & 511;
            int row = rem >> 3;
            int c8  = (rem & 7) * 8;
            const __half* gsrc = ((arr == 0) ? Kr : (arr == 1) ? Ki : Vv)
                                 + (size_t)(kt*64 + row)*DH + c8;
            cpa16(sm_u32(kvs + s*KVSTG + arr*64*KPAD + row*KPAD + c8), gsrc);
        }
    };

    // stage Q tiles (synchronous, one-time)
    {
        const uint4* src[2] = {
            (const uint4*)(g_hi + ((size_t)(0*BH + bh) * SQ + q0) * DH),
            (const uint4*)(g_hi + ((size_t)(1*BH + bh) * SQ + q0) * DH)};
        #pragma unroll
        for (int it = 0; it < 8; it++) {
            int idx = tid + it*256;
            int arr = idx >> 10;
            int rem = idx & 1023;
            int row = rem >> 3;
            int c8  = rem & 7;
            *(uint4*)(qs + arr*128*KPAD + row*KPAD + c8*8) = src[arr][row*8 + c8];
        }
    }
    load_kv(0, 0); cp_commit();
    __syncthreads();

    uint32_t a_qr[4][4], a_qi[4][4];
    {
        int r = lane & 15, sg = lane >> 4;
        #pragma unroll
        for (int c = 0; c < 4; c++) {
            ldsm4(a_qr[c], sm_u32(qs + 0*128*KPAD + (w*16 + r)*KPAD + c*16 + sg*8));
            ldsm4(a_qi[c], sm_u32(qs + 1*128*KPAD + (w*16 + r)*KPAD + c*16 + sg*8));
        }
    }

    float o_acc[8][4];
    #pragma unroll
    for (int t = 0; t < 8; t++)
        #pragma unroll
        for (int j = 0; j < 4; j++) o_acc[t][j] = 0.f;
    float m_[2] = {-1e30f, -1e30f};
    float l_[2] = {0.f, 0.f};

    const int q8 = lane >> 3, rr = lane & 7;

    for (int kt = 0; kt < SQ/64; kt++) {
        if (kt + 1 < SQ/64) { load_kv((kt+1) & 1, kt+1); cp_commit(); cp_wait<1>(); }
        else                cp_wait<0>();
        __syncthreads();

        const __half* krp = kvs + (kt & 1)*KVSTG;
        const __half* kip = krp + 64*KPAD;
        const __half* vp  = krp + 2*64*KPAD;

        // scores: sr = qr.kr + qi.ki ; si = qi.kr - qr.ki
        float sr[8][4], si[8][4];
        #pragma unroll
        for (int t = 0; t < 8; t++)
            #pragma unroll
            for (int j = 0; j < 4; j++) { sr[t][j] = 0.f; si[t][j] = 0.f; }

        #pragma unroll
        for (int c = 0; c < 4; c++) {
            #pragma unroll
            for (int tp = 0; tp < 4; tp++) {
                int row = tp*16 + (q8 >> 1)*8 + rr;
                int col = c*16 + (q8 & 1)*8;
                uint32_t br[4], bi[4];
                ldsm4(br, sm_u32(krp + row*KPAD + col));
                ldsm4(bi, sm_u32(kip + row*KPAD + col));
                #pragma unroll
                for (int tt = 0; tt < 2; tt++) {
                    int t = tp*2 + tt;
                    mma16816(sr[t], a_qr[c], br[2*tt], br[2*tt+1]);
                    mma16816(sr[t], a_qi[c], bi[2*tt], bi[2*tt+1]);
                    mma16816(si[t], a_qi[c], br[2*tt], br[2*tt+1]);
                    mma16816(si[t], a_qr[c],
                             bi[2*tt] ^ 0x80008000u, bi[2*tt+1] ^ 0x80008000u);
                }
            }
        }

        // magnitude + online softmax
        float pv_[2][16];
        #pragma unroll
        for (int h = 0; h < 2; h++) {
            float sv[16];
            float mx = m_[h];
            #pragma unroll
            for (int t = 0; t < 8; t++)
                #pragma unroll
                for (int j = 0; j < 2; j++) {
                    float a = sr[t][2*h + j], b = si[t][2*h + j];
                    float s = sqrtf(fmaf(a, a, b*b)) * 0.125f;
                    sv[t*2 + j] = s;
                    mx = fmaxf(mx, s);
                }
            mx = fmaxf(mx, __shfl_xor_sync(0xffffffffu, mx, 1));
            mx = fmaxf(mx, __shfl_xor_sync(0xffffffffu, mx, 2));
            float corr = __expf(m_[h] - mx);
            float sum = 0.f;
            #pragma unroll
            for (int kk = 0; kk < 16; kk++) {
                float p = __expf(sv[kk] - mx);
                pv_[h][kk] = p;
                sum += p;
            }
            sum += __shfl_xor_sync(0xffffffffu, sum, 1);
            sum += __shfl_xor_sync(0xffffffffu, sum, 2);
            l_[h] = l_[h]*corr + sum;
            m_[h] = mx;
            #pragma unroll
            for (int t = 0; t < 8; t++) {
                o_acc[t][2*h]   *= corr;
                o_acc[t][2*h+1] *= corr;
            }
        }

        // P -> fp16 A-frags (C-frag layout == A-frag layout)
        uint32_t pah[4][4];
        #pragma unroll
        for (int c = 0; c < 4; c++)
            #pragma unroll
            for (int tt = 0; tt < 2; tt++)
                #pragma unroll
                for (int h = 0; h < 2; h++) {
                    int t = 2*c + tt;
                    __half2 hh = __floats2half2_rn(pv_[h][2*t], pv_[h][2*t + 1]);
                    pah[c][tt*2 + h] = *reinterpret_cast<uint32_t*>(&hh);
                }

        // O += P @ V
        #pragma unroll
        for (int c = 0; c < 4; c++) {
            #pragma unroll
            for (int tp = 0; tp < 4; tp++) {
                int row = c*16 + (q8 & 1)*8 + rr;
                int col = tp*16 + (q8 >> 1)*8;
                uint32_t bv[4];
                ldsm4t(bv, sm_u32(vp + row*KPAD + col));
                mma16816(o_acc[2*tp],     pah[c], bv[0], bv[1]);
                mma16816(o_acc[2*tp + 1], pah[c], bv[2], bv[3]);
            }
        }
        __syncthreads();
    }

    // epilogue
    const int b_ = bh / NH, hd = bh % NH;
    const int g  = lane >> 2, nj = (lane & 3)*2;
    #pragma unroll
    for (int h = 0; h < 2; h++) {
        float inv = 1.0f / l_[h];
        int row = q0 + w*16 + g + h*8;
        float* orow = out + (size_t)(b_*SQ + row)*DIM + hd*DH;
        #pragma unroll
        for (int t = 0; t < 8; t++) {
            float2 v2 = make_float2(o_acc[t][2*h]*inv, o_acc[t][2*h+1]*inv);
            *(float2*)(orow + t*8 + nj) = v2;
        }
    }
}

// ---------------------------------------------------------------------------
extern "C" void kernel_launch(void* const* d_in, const int* in_sizes, int n_in,
                              void* d_out, int out_size)
{
    const float* X   = (const float*)d_in[0];
    const float* Wqr = (const float*)d_in[1];
    const float* Wqi = (const float*)d_in[2];
    const float* Wkr = (const float*)d_in[3];
    const float* Wki = (const float*)d_in[4];
    const float* Wv  = (const float*)d_in[5];
    float* out = (float*)d_out;

    const int proj_smem = 2 * PSTG * (int)sizeof(__half);                // 110592
    const int attn_smem = (2*128*KPAD + 2*KVSTG) * (int)sizeof(__half);  // 92160
    cudaFuncSetAttribute(proj_mma_kernel, cudaFuncAttributeMaxDynamicSharedMemorySize, proj_smem);
    cudaFuncSetAttribute(attn_kernel, cudaFuncAttributeMaxDynamicSharedMemorySize, attn_smem);

    split_kernel<<<1024, 256>>>(X, Wqr, Wqi, Wkr, Wki, Wv);
    proj_mma_kernel<<<dim3(30, 32), 256, proj_smem>>>();
    attn_kernel<<<dim3(SQ/128, BH), 256, attn_smem>>>(out);
}

// round 10
// speedup vs baseline: 6.8098x; 1.2691x over previous
#include <cuda_runtime.h>
#include <cuda_fp16.h>
#include <cstdint>

// Problem constants
#define SQ   2048
#define DIM  768
#define NH   12
#define DH   64
#define NB   2
#define BH   (NB*NH)   // 24

// fp16 scratch: [5][BH][S][DH]  (qr,qi,kr,ki,v) — hi (rn-rounded) only
__device__ __align__(16) __half g_hi[5u * BH * SQ * DH];
// fp16 copies of inputs: X hi only; W hi+lo (weights keep full precision)
__device__ __align__(16) __half g_xhi[4096u * DIM];
__device__ __align__(16) __half g_whi[5u * DIM * DIM], g_wlo[5u * DIM * DIM];

// ---------------------------------------------------------------------------
// helpers
// ---------------------------------------------------------------------------
__device__ __forceinline__ uint32_t sm_u32(const void* p) {
    return (uint32_t)__cvta_generic_to_shared(p);
}
__device__ __forceinline__ void ldsm4(uint32_t* r, uint32_t a) {
    asm volatile("ldmatrix.sync.aligned.m8n8.x4.shared.b16 {%0,%1,%2,%3}, [%4];"
                 : "=r"(r[0]), "=r"(r[1]), "=r"(r[2]), "=r"(r[3]) : "r"(a));
}
__device__ __forceinline__ void ldsm4t(uint32_t* r, uint32_t a) {
    asm volatile("ldmatrix.sync.aligned.m8n8.x4.trans.shared.b16 {%0,%1,%2,%3}, [%4];"
                 : "=r"(r[0]), "=r"(r[1]), "=r"(r[2]), "=r"(r[3]) : "r"(a));
}
__device__ __forceinline__ void mma16816(float* c, const uint32_t* a,
                                         uint32_t b0, uint32_t b1) {
    asm volatile(
        "mma.sync.aligned.m16n8k16.row.col.f32.f16.f16.f32 "
        "{%0,%1,%2,%3},{%4,%5,%6,%7},{%8,%9},{%0,%1,%2,%3};"
        : "+f"(c[0]), "+f"(c[1]), "+f"(c[2]), "+f"(c[3])
        : "r"(a[0]), "r"(a[1]), "r"(a[2]), "r"(a[3]), "r"(b0), "r"(b1));
}
__device__ __forceinline__ void cpa16(uint32_t d, const void* s) {
    asm volatile("cp.async.cg.shared.global [%0], [%1], 16;" :: "r"(d), "l"(s));
}
__device__ __forceinline__ void cp_commit() { asm volatile("cp.async.commit_group;"); }
template<int N> __device__ __forceinline__ void cp_wait() {
    asm volatile("cp.async.wait_group %0;" :: "n"(N));
}
__device__ __forceinline__ float fsqrt_approx(float x) {
    float y;
    asm("sqrt.approx.ftz.f32 %0, %1;" : "=f"(y) : "f"(x));
    return y;
}

// ---------------------------------------------------------------------------
// Kernel 0: split fp32 inputs -> fp16 (X: hi; W: hi+lo)
// ---------------------------------------------------------------------------
__global__ __launch_bounds__(256) void split_kernel(
    const float* __restrict__ X,
    const float* __restrict__ W0, const float* __restrict__ W1,
    const float* __restrict__ W2, const float* __restrict__ W3,
    const float* __restrict__ W4)
{
    const int64_t NX4 = (int64_t)4096 * DIM / 4;
    const int64_t NW4 = (int64_t)DIM * DIM / 4;
    const int64_t total4 = NX4 + 5 * NW4;
    for (int64_t i4 = (int64_t)blockIdx.x * 256 + threadIdx.x;
         i4 < total4; i4 += (int64_t)gridDim.x * 256) {
        if (i4 < NX4) {
            float4 v = ((const float4*)X)[i4];
            __half2* dh = (__half2*)g_xhi + i4*2;
            dh[0] = __floats2half2_rn(v.x, v.y);
            dh[1] = __floats2half2_rn(v.z, v.w);
        } else {
            int64_t j = i4 - NX4;
            int ws = (int)(j / NW4);
            int64_t rem = j - (int64_t)ws * NW4;
            const float* Wp = (ws == 0) ? W0 : (ws == 1) ? W1 :
                              (ws == 2) ? W2 : (ws == 3) ? W3 : W4;
            float4 v = ((const float4*)Wp)[rem];
            __half2* dh = (__half2*)g_whi + j*2;
            __half2* dl = (__half2*)g_wlo + j*2;
            __half hx = __float2half_rn(v.x), hy = __float2half_rn(v.y);
            __half hz = __float2half_rn(v.z), hw = __float2half_rn(v.w);
            dh[0] = __halves2half2(hx, hy);
            dh[1] = __halves2half2(hz, hw);
            dl[0] = __halves2half2(__float2half_rn(v.x - __half2float(hx)),
                                   __float2half_rn(v.y - __half2float(hy)));
            dl[1] = __halves2half2(__float2half_rn(v.z - __half2float(hz)),
                                   __float2half_rn(v.w - __half2float(hw)));
        }
    }
}

// ---------------------------------------------------------------------------
// Kernel 1: tensor-core projections.  C = X @ W^T, 2-segment: Ahi*(Bhi+Blo).
// CTA 128x128, 8 warps (2x4), warp tile 64x32. cp.async double-buffered k64.
// ---------------------------------------------------------------------------
#define PKP  72
#define PSTG (3*128*PKP)   // halves per stage (Ahi,Bhi,Blo)

__global__ __launch_bounds__(256) void proj_mma_kernel()
{
    extern __shared__ __half sp[];
    const int tid  = threadIdx.x;
    const int lane = tid & 31;
    const int w    = tid >> 5;
    const int bx      = blockIdx.x;
    const int which   = bx / 6;
    const int colBase = (bx % 6) * 128;
    const int rowBase = blockIdx.y * 128;

    const __half* Ahi = g_xhi;
    const __half* Bhi = g_whi + (size_t)which * DIM * DIM;
    const __half* Blo = g_wlo + (size_t)which * DIM * DIM;

    auto load_stage = [&](int s, int k0) {
        #pragma unroll
        for (int it = 0; it < 12; it++) {
            int idx = tid + it*256;          // < 3072
            int arr = idx >> 10;             // 0..2
            int rem = idx & 1023;
            int row = rem >> 3;
            int c8  = (rem & 7) * 8;
            const __half* gsrc;
            if (arr == 0)      gsrc = Ahi + (size_t)(rowBase + row)*DIM + k0 + c8;
            else if (arr == 1) gsrc = Bhi + (size_t)(colBase + row)*DIM + k0 + c8;
            else               gsrc = Blo + (size_t)(colBase + row)*DIM + k0 + c8;
            cpa16(sm_u32(sp + s*PSTG + arr*128*PKP + row*PKP + c8), gsrc);
        }
    };

    float acc[4][4][4];
    #pragma unroll
    for (int mt = 0; mt < 4; mt++)
        #pragma unroll
        for (int nt = 0; nt < 4; nt++)
            #pragma unroll
            for (int j = 0; j < 4; j++) acc[mt][nt][j] = 0.f;

    const int r  = lane & 15, sg = lane >> 4;
    const int q8 = lane >> 3, rr = lane & 7;
    const int wRow = (w >> 2) * 64;
    const int wCol = (w & 3) * 32;

    load_stage(0, 0); cp_commit();

    #pragma unroll 1
    for (int it = 0; it < 12; it++) {
        if (it + 1 < 12) { load_stage((it+1) & 1, (it+1)*64); cp_commit(); cp_wait<1>(); }
        else             cp_wait<0>();
        __syncthreads();

        const __half* A0 = sp + (it & 1)*PSTG;
        const __half* B0 = A0 + 128*PKP;
        const __half* B1 = A0 + 2*128*PKP;

        #pragma unroll
        for (int kc = 0; kc < 4; kc++) {
            uint32_t ah[4][4], bh[2][4], bl[2][4];
            #pragma unroll
            for (int mt = 0; mt < 4; mt++)
                ldsm4(ah[mt], sm_u32(A0 + (wRow + mt*16 + r)*PKP + kc*16 + sg*8));
            #pragma unroll
            for (int np = 0; np < 2; np++) {
                int brow = (wCol + np*16 + (q8 >> 1)*8 + rr)*PKP + kc*16 + (q8 & 1)*8;
                ldsm4(bh[np], sm_u32(B0 + brow));
                ldsm4(bl[np], sm_u32(B1 + brow));
            }
            #pragma unroll
            for (int mt = 0; mt < 4; mt++)
                #pragma unroll
                for (int np = 0; np < 2; np++)
                    #pragma unroll
                    for (int tt = 0; tt < 2; tt++) {
                        float* c = acc[mt][np*2 + tt];
                        mma16816(c, ah[mt], bh[np][2*tt], bh[np][2*tt+1]);
                        mma16816(c, ah[mt], bl[np][2*tt], bl[np][2*tt+1]);
                    }
        }
        __syncthreads();
    }

    // epilogue: write per-head fp16 scratch (half2 stores, d even)
    #pragma unroll
    for (int mt = 0; mt < 4; mt++)
        #pragma unroll
        for (int nt = 0; nt < 4; nt++)
            #pragma unroll
            for (int jh = 0; jh < 2; jh++) {
                int row = rowBase + wRow + mt*16 + (lane >> 2) + jh*8;
                int col = colBase + wCol + nt*8 + (lane & 3)*2;
                int b_ = row >> 11, s_ = row & (SQ - 1);
                int h  = col >> 6,  d  = col & 63;
                size_t off = (((size_t)which*BH + (b_*NH + h))*SQ + s_)*DH + d;
                *(__half2*)(g_hi + off) =
                    __floats2half2_rn(acc[mt][nt][jh*2 + 0], acc[mt][nt][jh*2 + 1]);
            }
}

// ---------------------------------------------------------------------------
// Kernel 2: tensor-core complex flash attention (fp16, 1 segment).
// CTA = 64 q-rows x one bh, 4 warps (128 thr) -> 2 CTAs/SM for latency overlap.
// K/V tiles (kr,ki,v) cp.async double-buffered.
// ---------------------------------------------------------------------------
#define KPAD 72
#define KVSTG (3*64*KPAD)   // halves per KV stage
#define ATHR 128

__global__ __launch_bounds__(ATHR, 2) void attn_kernel(float* __restrict__ out)
{
    extern __shared__ __half smh[];
    __half* qs  = smh;                  // 2 * 64 * KPAD (qr, qi)
    __half* kvs = smh + 2*64*KPAD;      // 2 stages * (kr,ki,v) 64*KPAD each

    const int tid  = threadIdx.x;
    const int lane = tid & 31;
    const int w    = tid >> 5;          // 0..3
    const int bh   = blockIdx.y;
    const int q0   = blockIdx.x * 64;

    const __half* Kr = g_hi + (size_t)(2*BH + bh) * SQ * DH;
    const __half* Ki = g_hi + (size_t)(3*BH + bh) * SQ * DH;
    const __half* Vv = g_hi + (size_t)(4*BH + bh) * SQ * DH;

    auto load_kv = [&](int s, int kt) {
        #pragma unroll
        for (int it = 0; it < 12; it++) {
            int idx = tid + it*ATHR;         // < 1536
            int arr = idx >> 9;              // 0..2
            int rem = idx & 511;
            int row = rem >> 3;
            int c8  = (rem & 7) * 8;
            const __half* gsrc = ((arr == 0) ? Kr : (arr == 1) ? Ki : Vv)
                                 + (size_t)(kt*64 + row)*DH + c8;
            cpa16(sm_u32(kvs + s*KVSTG + arr*64*KPAD + row*KPAD + c8), gsrc);
        }
    };

    // stage Q tiles (synchronous, one-time): 2 arrays x 64 rows x 8 uint4
    {
        const uint4* src[2] = {
            (const uint4*)(g_hi + ((size_t)(0*BH + bh) * SQ + q0) * DH),
            (const uint4*)(g_hi + ((size_t)(1*BH + bh) * SQ + q0) * DH)};
        #pragma unroll
        for (int it = 0; it < 8; it++) {
            int idx = tid + it*ATHR;         // < 1024
            int arr = idx >> 9;
            int rem = idx & 511;
            int row = rem >> 3;
            int c8  = rem & 7;
            *(uint4*)(qs + arr*64*KPAD + row*KPAD + c8*8) = src[arr][row*8 + c8];
        }
    }
    load_kv(0, 0); cp_commit();
    __syncthreads();

    uint32_t a_qr[4][4], a_qi[4][4];
    {
        int r = lane & 15, sg = lane >> 4;
        #pragma unroll
        for (int c = 0; c < 4; c++) {
            ldsm4(a_qr[c], sm_u32(qs + 0*64*KPAD + (w*16 + r)*KPAD + c*16 + sg*8));
            ldsm4(a_qi[c], sm_u32(qs + 1*64*KPAD + (w*16 + r)*KPAD + c*16 + sg*8));
        }
    }

    float o_acc[8][4];
    #pragma unroll
    for (int t = 0; t < 8; t++)
        #pragma unroll
        for (int j = 0; j < 4; j++) o_acc[t][j] = 0.f;
    float m_[2] = {-1e30f, -1e30f};
    float l_[2] = {0.f, 0.f};

    const int q8 = lane >> 3, rr = lane & 7;

    for (int kt = 0; kt < SQ/64; kt++) {
        if (kt + 1 < SQ/64) { load_kv((kt+1) & 1, kt+1); cp_commit(); cp_wait<1>(); }
        else                cp_wait<0>();
        __syncthreads();

        const __half* krp = kvs + (kt & 1)*KVSTG;
        const __half* kip = krp + 64*KPAD;
        const __half* vp  = krp + 2*64*KPAD;

        // scores: sr = qr.kr + qi.ki ; si = qi.kr - qr.ki
        float sr[8][4], si[8][4];
        #pragma unroll
        for (int t = 0; t < 8; t++)
            #pragma unroll
            for (int j = 0; j < 4; j++) { sr[t][j] = 0.f; si[t][j] = 0.f; }

        #pragma unroll
        for (int c = 0; c < 4; c++) {
            #pragma unroll
            for (int tp = 0; tp < 4; tp++) {
                int row = tp*16 + (q8 >> 1)*8 + rr;
                int col = c*16 + (q8 & 1)*8;
                uint32_t br[4], bi[4];
                ldsm4(br, sm_u32(krp + row*KPAD + col));
                ldsm4(bi, sm_u32(kip + row*KPAD + col));
                #pragma unroll
                for (int tt = 0; tt < 2; tt++) {
                    int t = tp*2 + tt;
                    mma16816(sr[t], a_qr[c], br[2*tt], br[2*tt+1]);
                    mma16816(sr[t], a_qi[c], bi[2*tt], bi[2*tt+1]);
                    mma16816(si[t], a_qi[c], br[2*tt], br[2*tt+1]);
                    mma16816(si[t], a_qr[c],
                             bi[2*tt] ^ 0x80008000u, bi[2*tt+1] ^ 0x80008000u);
                }
            }
        }

        // magnitude + online softmax
        float pv_[2][16];
        #pragma unroll
        for (int h = 0; h < 2; h++) {
            float sv[16];
            float mx = m_[h];
            #pragma unroll
            for (int t = 0; t < 8; t++)
                #pragma unroll
                for (int j = 0; j < 2; j++) {
                    float a = sr[t][2*h + j], b = si[t][2*h + j];
                    float s = fsqrt_approx(fmaf(a, a, b*b)) * 0.125f;
                    sv[t*2 + j] = s;
                    mx = fmaxf(mx, s);
                }
            mx = fmaxf(mx, __shfl_xor_sync(0xffffffffu, mx, 1));
            mx = fmaxf(mx, __shfl_xor_sync(0xffffffffu, mx, 2));
            float corr = __expf(m_[h] - mx);
            float sum = 0.f;
            #pragma unroll
            for (int kk = 0; kk < 16; kk++) {
                float p = __expf(sv[kk] - mx);
                pv_[h][kk] = p;
                sum += p;
            }
            sum += __shfl_xor_sync(0xffffffffu, sum, 1);
            sum += __shfl_xor_sync(0xffffffffu, sum, 2);
            l_[h] = l_[h]*corr + sum;
            m_[h] = mx;
            #pragma unroll
            for (int t = 0; t < 8; t++) {
                o_acc[t][2*h]   *= corr;
                o_acc[t][2*h+1] *= corr;
            }
        }

        // P -> fp16 A-frags (C-frag layout == A-frag layout)
        uint32_t pah[4][4];
        #pragma unroll
        for (int c = 0; c < 4; c++)
            #pragma unroll
            for (int tt = 0; tt < 2; tt++)
                #pragma unroll
                for (int h = 0; h < 2; h++) {
                    int t = 2*c + tt;
                    __half2 hh = __floats2half2_rn(pv_[h][2*t], pv_[h][2*t + 1]);
                    pah[c][tt*2 + h] = *reinterpret_cast<uint32_t*>(&hh);
                }

        // O += P @ V
        #pragma unroll
        for (int c = 0; c < 4; c++) {
            #pragma unroll
            for (int tp = 0; tp < 4; tp++) {
                int row = c*16 + (q8 & 1)*8 + rr;
                int col = tp*16 + (q8 >> 1)*8;
                uint32_t bv[4];
                ldsm4t(bv, sm_u32(vp + row*KPAD + col));
                mma16816(o_acc[2*tp],     pah[c], bv[0], bv[1]);
                mma16816(o_acc[2*tp + 1], pah[c], bv[2], bv[3]);
            }
        }
        __syncthreads();
    }

    // epilogue
    const int b_ = bh / NH, hd = bh % NH;
    const int g  = lane >> 2, nj = (lane & 3)*2;
    #pragma unroll
    for (int h = 0; h < 2; h++) {
        float inv = 1.0f / l_[h];
        int row = q0 + w*16 + g + h*8;
        float* orow = out + (size_t)(b_*SQ + row)*DIM + hd*DH;
        #pragma unroll
        for (int t = 0; t < 8; t++) {
            float2 v2 = make_float2(o_acc[t][2*h]*inv, o_acc[t][2*h+1]*inv);
            *(float2*)(orow + t*8 + nj) = v2;
        }
    }
}

// ---------------------------------------------------------------------------
extern "C" void kernel_launch(void* const* d_in, const int* in_sizes, int n_in,
                              void* d_out, int out_size)
{
    const float* X   = (const float*)d_in[0];
    const float* Wqr = (const float*)d_in[1];
    const float* Wqi = (const float*)d_in[2];
    const float* Wkr = (const float*)d_in[3];
    const float* Wki = (const float*)d_in[4];
    const float* Wv  = (const float*)d_in[5];
    float* out = (float*)d_out;

    const int proj_smem = 2 * PSTG * (int)sizeof(__half);                // 110592
    const int attn_smem = (2*64*KPAD + 2*KVSTG) * (int)sizeof(__half);   // 73728
    cudaFuncSetAttribute(proj_mma_kernel, cudaFuncAttributeMaxDynamicSharedMemorySize, proj_smem);
    cudaFuncSetAttribute(attn_kernel, cudaFuncAttributeMaxDynamicSharedMemorySize, attn_smem);

    split_kernel<<<1024, 256>>>(X, Wqr, Wqi, Wkr, Wki, Wv);
    proj_mma_kernel<<<dim3(30, 32), 256, proj_smem>>>();
    attn_kernel<<<dim3(SQ/64, BH), ATHR, attn_smem>>>(out);
}

// round 11
// speedup vs baseline: 7.1907x; 1.0559x over previous
#include <cuda_runtime.h>
#include <cuda_fp16.h>
#include <cstdint>

// Problem constants
#define SQ   2048
#define DIM  768
#define NH   12
#define DH   64
#define NB   2
#define BH   (NB*NH)   // 24

// fp16 scratch: [5][BH][S][DH]  (qr,qi,kr,ki,v) — hi (rn-rounded) only
__device__ __align__(16) __half g_hi[5u * BH * SQ * DH];
// fp16 copies of inputs: X hi only; W hi+lo (weights keep full precision)
__device__ __align__(16) __half g_xhi[4096u * DIM];
__device__ __align__(16) __half g_whi[5u * DIM * DIM], g_wlo[5u * DIM * DIM];

// ---------------------------------------------------------------------------
// helpers
// ---------------------------------------------------------------------------
__device__ __forceinline__ uint32_t sm_u32(const void* p) {
    return (uint32_t)__cvta_generic_to_shared(p);
}
__device__ __forceinline__ void ldsm4(uint32_t* r, uint32_t a) {
    asm volatile("ldmatrix.sync.aligned.m8n8.x4.shared.b16 {%0,%1,%2,%3}, [%4];"
                 : "=r"(r[0]), "=r"(r[1]), "=r"(r[2]), "=r"(r[3]) : "r"(a));
}
__device__ __forceinline__ void ldsm4t(uint32_t* r, uint32_t a) {
    asm volatile("ldmatrix.sync.aligned.m8n8.x4.trans.shared.b16 {%0,%1,%2,%3}, [%4];"
                 : "=r"(r[0]), "=r"(r[1]), "=r"(r[2]), "=r"(r[3]) : "r"(a));
}
__device__ __forceinline__ void mma16816(float* c, const uint32_t* a,
                                         uint32_t b0, uint32_t b1) {
    asm volatile(
        "mma.sync.aligned.m16n8k16.row.col.f32.f16.f16.f32 "
        "{%0,%1,%2,%3},{%4,%5,%6,%7},{%8,%9},{%0,%1,%2,%3};"
        : "+f"(c[0]), "+f"(c[1]), "+f"(c[2]), "+f"(c[3])
        : "r"(a[0]), "r"(a[1]), "r"(a[2]), "r"(a[3]), "r"(b0), "r"(b1));
}
__device__ __forceinline__ void cpa16(uint32_t d, const void* s) {
    asm volatile("cp.async.cg.shared.global [%0], [%1], 16;" :: "r"(d), "l"(s));
}
__device__ __forceinline__ void cp_commit() { asm volatile("cp.async.commit_group;"); }
template<int N> __device__ __forceinline__ void cp_wait() {
    asm volatile("cp.async.wait_group %0;" :: "n"(N));
}
__device__ __forceinline__ float fsqrt_approx(float x) {
    float y;
    asm("sqrt.approx.ftz.f32 %0, %1;" : "=f"(y) : "f"(x));
    return y;
}

// ---------------------------------------------------------------------------
// Kernel 0: split fp32 inputs -> fp16 (X: hi; W: hi+lo)
// ---------------------------------------------------------------------------
__global__ __launch_bounds__(256) void split_kernel(
    const float* __restrict__ X,
    const float* __restrict__ W0, const float* __restrict__ W1,
    const float* __restrict__ W2, const float* __restrict__ W3,
    const float* __restrict__ W4)
{
    const int64_t NX4 = (int64_t)4096 * DIM / 4;
    const int64_t NW4 = (int64_t)DIM * DIM / 4;
    const int64_t total4 = NX4 + 5 * NW4;
    for (int64_t i4 = (int64_t)blockIdx.x * 256 + threadIdx.x;
         i4 < total4; i4 += (int64_t)gridDim.x * 256) {
        if (i4 < NX4) {
            float4 v = ((const float4*)X)[i4];
            __half2* dh = (__half2*)g_xhi + i4*2;
            dh[0] = __floats2half2_rn(v.x, v.y);
            dh[1] = __floats2half2_rn(v.z, v.w);
        } else {
            int64_t j = i4 - NX4;
            int ws = (int)(j / NW4);
            int64_t rem = j - (int64_t)ws * NW4;
            const float* Wp = (ws == 0) ? W0 : (ws == 1) ? W1 :
                              (ws == 2) ? W2 : (ws == 3) ? W3 : W4;
            float4 v = ((const float4*)Wp)[rem];
            __half2* dh = (__half2*)g_whi + j*2;
            __half2* dl = (__half2*)g_wlo + j*2;
            __half hx = __float2half_rn(v.x), hy = __float2half_rn(v.y);
            __half hz = __float2half_rn(v.z), hw = __float2half_rn(v.w);
            dh[0] = __halves2half2(hx, hy);
            dh[1] = __halves2half2(hz, hw);
            dl[0] = __halves2half2(__float2half_rn(v.x - __half2float(hx)),
                                   __float2half_rn(v.y - __half2float(hy)));
            dl[1] = __halves2half2(__float2half_rn(v.z - __half2float(hz)),
                                   __float2half_rn(v.w - __half2float(hw)));
        }
    }
}

// ---------------------------------------------------------------------------
// Kernel 1: tensor-core projections.  C = X @ W^T, 2-segment: Ahi*(Bhi+Blo).
// CTA 128x128, 4 warps (2x2), warp tile 64x64 -> 2 CTAs/SM.
// cp.async double-buffered k64.
// ---------------------------------------------------------------------------
#define PKP  72
#define PSTG (3*128*PKP)   // halves per stage (Ahi,Bhi,Blo)
#define PTHR 128

__global__ __launch_bounds__(PTHR, 2) void proj_mma_kernel()
{
    extern __shared__ __half sp[];
    const int tid  = threadIdx.x;
    const int lane = tid & 31;
    const int w    = tid >> 5;          // 0..3
    const int bx      = blockIdx.x;
    const int which   = bx / 6;
    const int colBase = (bx % 6) * 128;
    const int rowBase = blockIdx.y * 128;

    const __half* Ahi = g_xhi;
    const __half* Bhi = g_whi + (size_t)which * DIM * DIM;
    const __half* Blo = g_wlo + (size_t)which * DIM * DIM;

    auto load_stage = [&](int s, int k0) {
        #pragma unroll
        for (int it = 0; it < 24; it++) {
            int idx = tid + it*PTHR;         // < 3072
            int arr = idx >> 10;             // 0..2
            int rem = idx & 1023;
            int row = rem >> 3;
            int c8  = (rem & 7) * 8;
            const __half* gsrc;
            if (arr == 0)      gsrc = Ahi + (size_t)(rowBase + row)*DIM + k0 + c8;
            else if (arr == 1) gsrc = Bhi + (size_t)(colBase + row)*DIM + k0 + c8;
            else               gsrc = Blo + (size_t)(colBase + row)*DIM + k0 + c8;
            cpa16(sm_u32(sp + s*PSTG + arr*128*PKP + row*PKP + c8), gsrc);
        }
    };

    float acc[4][8][4];
    #pragma unroll
    for (int mt = 0; mt < 4; mt++)
        #pragma unroll
        for (int nt = 0; nt < 8; nt++)
            #pragma unroll
            for (int j = 0; j < 4; j++) acc[mt][nt][j] = 0.f;

    const int r  = lane & 15, sg = lane >> 4;
    const int q8 = lane >> 3, rr = lane & 7;
    const int wRow = (w >> 1) * 64;
    const int wCol = (w & 1) * 64;

    load_stage(0, 0); cp_commit();

    #pragma unroll 1
    for (int it = 0; it < 12; it++) {
        if (it + 1 < 12) { load_stage((it+1) & 1, (it+1)*64); cp_commit(); cp_wait<1>(); }
        else             cp_wait<0>();
        __syncthreads();

        const __half* A0 = sp + (it & 1)*PSTG;
        const __half* B0 = A0 + 128*PKP;
        const __half* B1 = A0 + 2*128*PKP;

        #pragma unroll
        for (int kc = 0; kc < 4; kc++) {
            uint32_t ah[4][4], bh[4][4], bl[4][4];
            #pragma unroll
            for (int mt = 0; mt < 4; mt++)
                ldsm4(ah[mt], sm_u32(A0 + (wRow + mt*16 + r)*PKP + kc*16 + sg*8));
            #pragma unroll
            for (int np = 0; np < 4; np++) {
                int brow = (wCol + np*16 + (q8 >> 1)*8 + rr)*PKP + kc*16 + (q8 & 1)*8;
                ldsm4(bh[np], sm_u32(B0 + brow));
                ldsm4(bl[np], sm_u32(B1 + brow));
            }
            #pragma unroll
            for (int mt = 0; mt < 4; mt++)
                #pragma unroll
                for (int np = 0; np < 4; np++)
                    #pragma unroll
                    for (int tt = 0; tt < 2; tt++) {
                        float* c = acc[mt][np*2 + tt];
                        mma16816(c, ah[mt], bh[np][2*tt], bh[np][2*tt+1]);
                        mma16816(c, ah[mt], bl[np][2*tt], bl[np][2*tt+1]);
                    }
        }
        __syncthreads();
    }

    // epilogue: write per-head fp16 scratch (half2 stores, d even)
    #pragma unroll
    for (int mt = 0; mt < 4; mt++)
        #pragma unroll
        for (int nt = 0; nt < 8; nt++)
            #pragma unroll
            for (int jh = 0; jh < 2; jh++) {
                int row = rowBase + wRow + mt*16 + (lane >> 2) + jh*8;
                int col = colBase + wCol + nt*8 + (lane & 3)*2;
                int b_ = row >> 11, s_ = row & (SQ - 1);
                int h  = col >> 6,  d  = col & 63;
                size_t off = (((size_t)which*BH + (b_*NH + h))*SQ + s_)*DH + d;
                *(__half2*)(g_hi + off) =
                    __floats2half2_rn(acc[mt][nt][jh*2 + 0], acc[mt][nt][jh*2 + 1]);
            }
}

// ---------------------------------------------------------------------------
// Kernel 2: tensor-core complex flash attention (fp16, 1 segment).
// CTA = 64 q-rows x one bh, 4 warps (128 thr) -> 2 CTAs/SM for latency overlap.
// K/V tiles (kr,ki,v) cp.async double-buffered.
// ---------------------------------------------------------------------------
#define KPAD 72
#define KVSTG (3*64*KPAD)   // halves per KV stage
#define ATHR 128

__global__ __launch_bounds__(ATHR, 2) void attn_kernel(float* __restrict__ out)
{
    extern __shared__ __half smh[];
    __half* qs  = smh;                  // 2 * 64 * KPAD (qr, qi)
    __half* kvs = smh + 2*64*KPAD;      // 2 stages * (kr,ki,v) 64*KPAD each

    const int tid  = threadIdx.x;
    const int lane = tid & 31;
    const int w    = tid >> 5;          // 0..3
    const int bh   = blockIdx.y;
    const int q0   = blockIdx.x * 64;

    const __half* Kr = g_hi + (size_t)(2*BH + bh) * SQ * DH;
    const __half* Ki = g_hi + (size_t)(3*BH + bh) * SQ * DH;
    const __half* Vv = g_hi + (size_t)(4*BH + bh) * SQ * DH;

    auto load_kv = [&](int s, int kt) {
        #pragma unroll
        for (int it = 0; it < 12; it++) {
            int idx = tid + it*ATHR;         // < 1536
            int arr = idx >> 9;              // 0..2
            int rem = idx & 511;
            int row = rem >> 3;
            int c8  = (rem & 7) * 8;
            const __half* gsrc = ((arr == 0) ? Kr : (arr == 1) ? Ki : Vv)
                                 + (size_t)(kt*64 + row)*DH + c8;
            cpa16(sm_u32(kvs + s*KVSTG + arr*64*KPAD + row*KPAD + c8), gsrc);
        }
    };

    // stage Q tiles (synchronous, one-time): 2 arrays x 64 rows x 8 uint4
    {
        const uint4* src[2] = {
            (const uint4*)(g_hi + ((size_t)(0*BH + bh) * SQ + q0) * DH),
            (const uint4*)(g_hi + ((size_t)(1*BH + bh) * SQ + q0) * DH)};
        #pragma unroll
        for (int it = 0; it < 8; it++) {
            int idx = tid + it*ATHR;         // < 1024
            int arr = idx >> 9;
            int rem = idx & 511;
            int row = rem >> 3;
            int c8  = rem & 7;
            *(uint4*)(qs + arr*64*KPAD + row*KPAD + c8*8) = src[arr][row*8 + c8];
        }
    }
    load_kv(0, 0); cp_commit();
    __syncthreads();

    uint32_t a_qr[4][4], a_qi[4][4];
    {
        int r = lane & 15, sg = lane >> 4;
        #pragma unroll
        for (int c = 0; c < 4; c++) {
            ldsm4(a_qr[c], sm_u32(qs + 0*64*KPAD + (w*16 + r)*KPAD + c*16 + sg*8));
            ldsm4(a_qi[c], sm_u32(qs + 1*64*KPAD + (w*16 + r)*KPAD + c*16 + sg*8));
        }
    }

    float o_acc[8][4];
    #pragma unroll
    for (int t = 0; t < 8; t++)
        #pragma unroll
        for (int j = 0; j < 4; j++) o_acc[t][j] = 0.f;
    float m_[2] = {-1e30f, -1e30f};
    float l_[2] = {0.f, 0.f};

    const int q8 = lane >> 3, rr = lane & 7;

    for (int kt = 0; kt < SQ/64; kt++) {
        if (kt + 1 < SQ/64) { load_kv((kt+1) & 1, kt+1); cp_commit(); cp_wait<1>(); }
        else                cp_wait<0>();
        __syncthreads();

        const __half* krp = kvs + (kt & 1)*KVSTG;
        const __half* kip = krp + 64*KPAD;
        const __half* vp  = krp + 2*64*KPAD;

        // scores: sr = qr.kr + qi.ki ; si = qi.kr - qr.ki
        float sr[8][4], si[8][4];
        #pragma unroll
        for (int t = 0; t < 8; t++)
            #pragma unroll
            for (int j = 0; j < 4; j++) { sr[t][j] = 0.f; si[t][j] = 0.f; }

        #pragma unroll
        for (int c = 0; c < 4; c++) {
            #pragma unroll
            for (int tp = 0; tp < 4; tp++) {
                int row = tp*16 + (q8 >> 1)*8 + rr;
                int col = c*16 + (q8 & 1)*8;
                uint32_t br[4], bi[4];
                ldsm4(br, sm_u32(krp + row*KPAD + col));
                ldsm4(bi, sm_u32(kip + row*KPAD + col));
                #pragma unroll
                for (int tt = 0; tt < 2; tt++) {
                    int t = tp*2 + tt;
                    mma16816(sr[t], a_qr[c], br[2*tt], br[2*tt+1]);
                    mma16816(sr[t], a_qi[c], bi[2*tt], bi[2*tt+1]);
                    mma16816(si[t], a_qi[c], br[2*tt], br[2*tt+1]);
                    mma16816(si[t], a_qr[c],
                             bi[2*tt] ^ 0x80008000u, bi[2*tt+1] ^ 0x80008000u);
                }
            }
        }

        // magnitude + online softmax
        float pv_[2][16];
        #pragma unroll
        for (int h = 0; h < 2; h++) {
            float sv[16];
            float mx = m_[h];
            #pragma unroll
            for (int t = 0; t < 8; t++)
                #pragma unroll
                for (int j = 0; j < 2; j++) {
                    float a = sr[t][2*h + j], b = si[t][2*h + j];
                    float s = fsqrt_approx(fmaf(a, a, b*b)) * 0.125f;
                    sv[t*2 + j] = s;
                    mx = fmaxf(mx, s);
                }
            mx = fmaxf(mx, __shfl_xor_sync(0xffffffffu, mx, 1));
            mx = fmaxf(mx, __shfl_xor_sync(0xffffffffu, mx, 2));
            float corr = __expf(m_[h] - mx);
            float sum = 0.f;
            #pragma unroll
            for (int kk = 0; kk < 16; kk++) {
                float p = __expf(sv[kk] - mx);
                pv_[h][kk] = p;
                sum += p;
            }
            sum += __shfl_xor_sync(0xffffffffu, sum, 1);
            sum += __shfl_xor_sync(0xffffffffu, sum, 2);
            l_[h] = l_[h]*corr + sum;
            m_[h] = mx;
            #pragma unroll
            for (int t = 0; t < 8; t++) {
                o_acc[t][2*h]   *= corr;
                o_acc[t][2*h+1] *= corr;
            }
        }

        // P -> fp16 A-frags (C-frag layout == A-frag layout)
        uint32_t pah[4][4];
        #pragma unroll
        for (int c = 0; c < 4; c++)
            #pragma unroll
            for (int tt = 0; tt < 2; tt++)
                #pragma unroll
                for (int h = 0; h < 2; h++) {
                    int t = 2*c + tt;
                    __half2 hh = __floats2half2_rn(pv_[h][2*t], pv_[h][2*t + 1]);
                    pah[c][tt*2 + h] = *reinterpret_cast<uint32_t*>(&hh);
                }

        // O += P @ V
        #pragma unroll
        for (int c = 0; c < 4; c++) {
            #pragma unroll
            for (int tp = 0; tp < 4; tp++) {
                int row = c*16 + (q8 & 1)*8 + rr;
                int col = tp*16 + (q8 >> 1)*8;
                uint32_t bv[4];
                ldsm4t(bv, sm_u32(vp + row*KPAD + col));
                mma16816(o_acc[2*tp],     pah[c], bv[0], bv[1]);
                mma16816(o_acc[2*tp + 1], pah[c], bv[2], bv[3]);
            }
        }
        __syncthreads();
    }

    // epilogue
    const int b_ = bh / NH, hd = bh % NH;
    const int g  = lane >> 2, nj = (lane & 3)*2;
    #pragma unroll
    for (int h = 0; h < 2; h++) {
        float inv = 1.0f / l_[h];
        int row = q0 + w*16 + g + h*8;
        float* orow = out + (size_t)(b_*SQ + row)*DIM + hd*DH;
        #pragma unroll
        for (int t = 0; t < 8; t++) {
            float2 v2 = make_float2(o_acc[t][2*h]*inv, o_acc[t][2*h+1]*inv);
            *(float2*)(orow + t*8 + nj) = v2;
        }
    }
}

// ---------------------------------------------------------------------------
extern "C" void kernel_launch(void* const* d_in, const int* in_sizes, int n_in,
                              void* d_out, int out_size)
{
    const float* X   = (const float*)d_in[0];
    const float* Wqr = (const float*)d_in[1];
    const float* Wqi = (const float*)d_in[2];
    const float* Wkr = (const float*)d_in[3];
    const float* Wki = (const float*)d_in[4];
    const float* Wv  = (const float*)d_in[5];
    float* out = (float*)d_out;

    const int proj_smem = 2 * PSTG * (int)sizeof(__half);                // 110592
    const int attn_smem = (2*64*KPAD + 2*KVSTG) * (int)sizeof(__half);   // 73728
    cudaFuncSetAttribute(proj_mma_kernel, cudaFuncAttributeMaxDynamicSharedMemorySize, proj_smem);
    cudaFuncSetAttribute(attn_kernel, cudaFuncAttributeMaxDynamicSharedMemorySize, attn_smem);

    split_kernel<<<1024, 256>>>(X, Wqr, Wqi, Wkr, Wki, Wv);
    proj_mma_kernel<<<dim3(30, 32), PTHR, proj_smem>>>();
    attn_kernel<<<dim3(SQ/64, BH), ATHR, attn_smem>>>(out);
}

// round 14
// speedup vs baseline: 8.8035x; 1.2243x over previous
#include <cuda_runtime.h>
#include <cuda_fp16.h>
#include <cstdint>

// Problem constants
#define SQ   2048
#define DIM  768
#define NH   12
#define DH   64
#define NB   2
#define BH   (NB*NH)   // 24

// fp16 scratch: [5][BH][S][DH]  (qr,qi,kr,ki,v)
__device__ __align__(16) __half g_hi[5u * BH * SQ * DH];
// fp16 copies of inputs
__device__ __align__(16) __half g_xhi[4096u * DIM];
__device__ __align__(16) __half g_whi[5u * DIM * DIM];

// ---------------------------------------------------------------------------
// helpers
// ---------------------------------------------------------------------------
__device__ __forceinline__ uint32_t sm_u32(const void* p) {
    return (uint32_t)__cvta_generic_to_shared(p);
}
__device__ __forceinline__ void ldsm4(uint32_t* r, uint32_t a) {
    asm volatile("ldmatrix.sync.aligned.m8n8.x4.shared.b16 {%0,%1,%2,%3}, [%4];"
                 : "=r"(r[0]), "=r"(r[1]), "=r"(r[2]), "=r"(r[3]) : "r"(a));
}
__device__ __forceinline__ void ldsm4t(uint32_t* r, uint32_t a) {
    asm volatile("ldmatrix.sync.aligned.m8n8.x4.trans.shared.b16 {%0,%1,%2,%3}, [%4];"
                 : "=r"(r[0]), "=r"(r[1]), "=r"(r[2]), "=r"(r[3]) : "r"(a));
}
__device__ __forceinline__ void mma16816(float* c, const uint32_t* a,
                                         uint32_t b0, uint32_t b1) {
    asm volatile(
        "mma.sync.aligned.m16n8k16.row.col.f32.f16.f16.f32 "
        "{%0,%1,%2,%3},{%4,%5,%6,%7},{%8,%9},{%0,%1,%2,%3};"
        : "+f"(c[0]), "+f"(c[1]), "+f"(c[2]), "+f"(c[3])
        : "r"(a[0]), "r"(a[1]), "r"(a[2]), "r"(a[3]), "r"(b0), "r"(b1));
}
__device__ __forceinline__ void cpa16(uint32_t d, const void* s) {
    asm volatile("cp.async.cg.shared.global [%0], [%1], 16;" :: "r"(d), "l"(s));
}
__device__ __forceinline__ void cp_commit() { asm volatile("cp.async.commit_group;"); }
template<int N> __device__ __forceinline__ void cp_wait() {
    asm volatile("cp.async.wait_group %0;" :: "n"(N));
}
__device__ __forceinline__ float fsqrt_approx(float x) {
    float y;
    asm("sqrt.approx.ftz.f32 %0, %1;" : "=f"(y) : "f"(x));
    return y;
}
__device__ __forceinline__ uint32_t hadd2u(uint32_t a, uint32_t b) {
    __half2 r = __hadd2(*(__half2*)&a, *(__half2*)&b);
    return *(uint32_t*)&r;
}
__device__ __forceinline__ uint32_t hsub2u(uint32_t a, uint32_t b) {
    __half2 r = __hsub2(*(__half2*)&a, *(__half2*)&b);
    return *(uint32_t*)&r;
}

// ---------------------------------------------------------------------------
// Kernel 0: convert fp32 inputs -> fp16 (X and W, hi only)
// ---------------------------------------------------------------------------
__global__ __launch_bounds__(256) void split_kernel(
    const float* __restrict__ X,
    const float* __restrict__ W0, const float* __restrict__ W1,
    const float* __restrict__ W2, const float* __restrict__ W3,
    const float* __restrict__ W4)
{
    const int64_t NX4 = (int64_t)4096 * DIM / 4;
    const int64_t NW4 = (int64_t)DIM * DIM / 4;
    const int64_t total4 = NX4 + 5 * NW4;
    for (int64_t i4 = (int64_t)blockIdx.x * 256 + threadIdx.x;
         i4 < total4; i4 += (int64_t)gridDim.x * 256) {
        if (i4 < NX4) {
            float4 v = ((const float4*)X)[i4];
            __half2* dh = (__half2*)g_xhi + i4*2;
            dh[0] = __floats2half2_rn(v.x, v.y);
            dh[1] = __floats2half2_rn(v.z, v.w);
        } else {
            int64_t j = i4 - NX4;
            int ws = (int)(j / NW4);
            int64_t rem = j - (int64_t)ws * NW4;
            const float* Wp = (ws == 0) ? W0 : (ws == 1) ? W1 :
                              (ws == 2) ? W2 : (ws == 3) ? W3 : W4;
            float4 v = ((const float4*)Wp)[rem];
            __half2* dh = (__half2*)g_whi + j*2;
            dh[0] = __floats2half2_rn(v.x, v.y);
            dh[1] = __floats2half2_rn(v.z, v.w);
        }
    }
}

// ---------------------------------------------------------------------------
// Kernel 1: tensor-core projections.  C = Xhi @ Whi^T (single segment).
// CTA 128x128, 4 warps (2x2), warp tile 64x64 -> 2 CTAs/SM.
// cp.async double-buffered k64.
// ---------------------------------------------------------------------------
#define PKP  72
#define PSTG (2*128*PKP)   // halves per stage (Ahi,Bhi)
#define PTHR 128

__global__ __launch_bounds__(PTHR, 2) void proj_mma_kernel()
{
    extern __shared__ __half sp[];
    const int tid  = threadIdx.x;
    const int lane = tid & 31;
    const int w    = tid >> 5;          // 0..3
    const int bx      = blockIdx.x;
    const int which   = bx / 6;
    const int colBase = (bx % 6) * 128;
    const int rowBase = blockIdx.y * 128;

    const __half* Ahi = g_xhi;
    const __half* Bhi = g_whi + (size_t)which * DIM * DIM;

    auto load_stage = [&](int s, int k0) {
        #pragma unroll
        for (int it = 0; it < 16; it++) {
            int idx = tid + it*PTHR;         // < 2048
            int arr = idx >> 10;             // 0..1
            int rem = idx & 1023;
            int row = rem >> 3;
            int c8  = (rem & 7) * 8;
            const __half* gsrc = (arr == 0)
                ? Ahi + (size_t)(rowBase + row)*DIM + k0 + c8
                : Bhi + (size_t)(colBase + row)*DIM + k0 + c8;
            cpa16(sm_u32(sp + s*PSTG + arr*128*PKP + row*PKP + c8), gsrc);
        }
    };

    float acc[4][8][4];
    #pragma unroll
    for (int mt = 0; mt < 4; mt++)
        #pragma unroll
        for (int nt = 0; nt < 8; nt++)
            #pragma unroll
            for (int j = 0; j < 4; j++) acc[mt][nt][j] = 0.f;

    const int r  = lane & 15, sg = lane >> 4;
    const int q8 = lane >> 3, rr = lane & 7;
    const int wRow = (w >> 1) * 64;
    const int wCol = (w & 1) * 64;

    load_stage(0, 0); cp_commit();

    #pragma unroll 1
    for (int it = 0; it < 12; it++) {
        if (it + 1 < 12) { load_stage((it+1) & 1, (it+1)*64); cp_commit(); cp_wait<1>(); }
        else             cp_wait<0>();
        __syncthreads();

        const __half* A0 = sp + (it & 1)*PSTG;
        const __half* B0 = A0 + 128*PKP;

        #pragma unroll
        for (int kc = 0; kc < 4; kc++) {
            uint32_t ah[4][4], bh[4][4];
            #pragma unroll
            for (int mt = 0; mt < 4; mt++)
                ldsm4(ah[mt], sm_u32(A0 + (wRow + mt*16 + r)*PKP + kc*16 + sg*8));
            #pragma unroll
            for (int np = 0; np < 4; np++) {
                int brow = (wCol + np*16 + (q8 >> 1)*8 + rr)*PKP + kc*16 + (q8 & 1)*8;
                ldsm4(bh[np], sm_u32(B0 + brow));
            }
            #pragma unroll
            for (int mt = 0; mt < 4; mt++)
                #pragma unroll
                for (int np = 0; np < 4; np++)
                    #pragma unroll
                    for (int tt = 0; tt < 2; tt++)
                        mma16816(acc[mt][np*2 + tt], ah[mt],
                                 bh[np][2*tt], bh[np][2*tt+1]);
        }
        __syncthreads();
    }

    // epilogue: write per-head fp16 scratch (half2 stores, d even)
    #pragma unroll
    for (int mt = 0; mt < 4; mt++)
        #pragma unroll
        for (int nt = 0; nt < 8; nt++)
            #pragma unroll
            for (int jh = 0; jh < 2; jh++) {
                int row = rowBase + wRow + mt*16 + (lane >> 2) + jh*8;
                int col = colBase + wCol + nt*8 + (lane & 3)*2;
                int b_ = row >> 11, s_ = row & (SQ - 1);
                int h  = col >> 6,  d  = col & 63;
                size_t off = (((size_t)which*BH + (b_*NH + h))*SQ + s_)*DH + d;
                *(__half2*)(g_hi + off) =
                    __floats2half2_rn(acc[mt][nt][jh*2 + 0], acc[mt][nt][jh*2 + 1]);
            }
}

// ---------------------------------------------------------------------------
// Kernel 2: tensor-core complex flash attention (fp16, Karatsuba 3-MMA scores).
// t1 = qr.kr, t2 = qi.ki, t3 = (qr+qi).(kr-ki)
// sr = t1+t2 ; si = (t3+t2)-t1
// CTA = 64 q-rows x one bh, 4 warps (128 thr) -> 2 CTAs/SM.
// ---------------------------------------------------------------------------
#define KPAD 72
#define KVSTG (3*64*KPAD)   // halves per KV stage
#define ATHR 128

__global__ __launch_bounds__(ATHR, 2) void attn_kernel(float* __restrict__ out)
{
    extern __shared__ __half smh[];
    __half* qs  = smh;                  // 2 * 64 * KPAD (qr, qi)
    __half* kvs = smh + 2*64*KPAD;      // 2 stages * (kr,ki,v) 64*KPAD each

    const int tid  = threadIdx.x;
    const int lane = tid & 31;
    const int w    = tid >> 5;          // 0..3
    const int bh   = blockIdx.y;
    const int q0   = blockIdx.x * 64;

    const __half* Kr = g_hi + (size_t)(2*BH + bh) * SQ * DH;
    const __half* Ki = g_hi + (size_t)(3*BH + bh) * SQ * DH;
    const __half* Vv = g_hi + (size_t)(4*BH + bh) * SQ * DH;

    auto load_kv = [&](int s, int kt) {
        #pragma unroll
        for (int it = 0; it < 12; it++) {
            int idx = tid + it*ATHR;         // < 1536
            int arr = idx >> 9;              // 0..2
            int rem = idx & 511;
            int row = rem >> 3;
            int c8  = (rem & 7) * 8;
            const __half* gsrc = ((arr == 0) ? Kr : (arr == 1) ? Ki : Vv)
                                 + (size_t)(kt*64 + row)*DH + c8;
            cpa16(sm_u32(kvs + s*KVSTG + arr*64*KPAD + row*KPAD + c8), gsrc);
        }
    };

    // stage Q tiles (synchronous, one-time): 2 arrays x 64 rows x 8 uint4
    {
        const uint4* src[2] = {
            (const uint4*)(g_hi + ((size_t)(0*BH + bh) * SQ + q0) * DH),
            (const uint4*)(g_hi + ((size_t)(1*BH + bh) * SQ + q0) * DH)};
        #pragma unroll
        for (int it = 0; it < 8; it++) {
            int idx = tid + it*ATHR;         // < 1024
            int arr = idx >> 9;
            int rem = idx & 511;
            int row = rem >> 3;
            int c8  = rem & 7;
            *(uint4*)(qs + arr*64*KPAD + row*KPAD + c8*8) = src[arr][row*8 + c8];
        }
    }
    load_kv(0, 0); cp_commit();
    __syncthreads();

    uint32_t a_qr[4][4], a_qi[4][4], a_qs[4][4];
    {
        int r = lane & 15, sg = lane >> 4;
        #pragma unroll
        for (int c = 0; c < 4; c++) {
            ldsm4(a_qr[c], sm_u32(qs + 0*64*KPAD + (w*16 + r)*KPAD + c*16 + sg*8));
            ldsm4(a_qi[c], sm_u32(qs + 1*64*KPAD + (w*16 + r)*KPAD + c*16 + sg*8));
            #pragma unroll
            for (int i = 0; i < 4; i++)
                a_qs[c][i] = hadd2u(a_qr[c][i], a_qi[c][i]);
        }
    }

    float o_acc[8][4];
    #pragma unroll
    for (int t = 0; t < 8; t++)
        #pragma unroll
        for (int j = 0; j < 4; j++) o_acc[t][j] = 0.f;
    float m_[2] = {-1e30f, -1e30f};
    float l_[2] = {0.f, 0.f};

    const int q8 = lane >> 3, rr = lane & 7;

    for (int kt = 0; kt < SQ/64; kt++) {
        if (kt + 1 < SQ/64) { load_kv((kt+1) & 1, kt+1); cp_commit(); cp_wait<1>(); }
        else                cp_wait<0>();
        __syncthreads();

        const __half* krp = kvs + (kt & 1)*KVSTG;
        const __half* kip = krp + 64*KPAD;
        const __half* vp  = krp + 2*64*KPAD;

        // Karatsuba score accumulators
        float t1[8][4], t2[8][4], t3[8][4];
        #pragma unroll
        for (int t = 0; t < 8; t++)
            #pragma unroll
            for (int j = 0; j < 4; j++) { t1[t][j] = 0.f; t2[t][j] = 0.f; t3[t][j] = 0.f; }

        #pragma unroll
        for (int c = 0; c < 4; c++) {
            #pragma unroll
            for (int tp = 0; tp < 4; tp++) {
                int row = tp*16 + (q8 >> 1)*8 + rr;
                int col = c*16 + (q8 & 1)*8;
                uint32_t br[4], bi[4], bs[4];
                ldsm4(br, sm_u32(krp + row*KPAD + col));
                ldsm4(bi, sm_u32(kip + row*KPAD + col));
                #pragma unroll
                for (int i = 0; i < 4; i++) bs[i] = hsub2u(br[i], bi[i]);
                #pragma unroll
                for (int tt = 0; tt < 2; tt++) {
                    int t = tp*2 + tt;
                    mma16816(t1[t], a_qr[c], br[2*tt], br[2*tt+1]);
                    mma16816(t2[t], a_qi[c], bi[2*tt], bi[2*tt+1]);
                    mma16816(t3[t], a_qs[c], bs[2*tt], bs[2*tt+1]);
                }
            }
        }

        // magnitude + online softmax; pack P to fp16 A-frags directly
        uint32_t pah[4][4];
        #pragma unroll
        for (int h = 0; h < 2; h++) {
            float sv[16];
            float mx = m_[h];
            #pragma unroll
            for (int t = 0; t < 8; t++)
                #pragma unroll
                for (int j = 0; j < 2; j++) {
                    float u1 = t1[t][2*h + j], u2 = t2[t][2*h + j], u3 = t3[t][2*h + j];
                    float a = u1 + u2;               // sr
                    float b = (u3 + u2) - u1;        // si
                    float s = fsqrt_approx(fmaf(a, a, b*b)) * 0.125f;
                    sv[t*2 + j] = s;
                    mx = fmaxf(mx, s);
                }
            mx = fmaxf(mx, __shfl_xor_sync(0xffffffffu, mx, 1));
            mx = fmaxf(mx, __shfl_xor_sync(0xffffffffu, mx, 2));
            float corr = __expf(m_[h] - mx);
            float sum = 0.f;
            #pragma unroll
            for (int t = 0; t < 8; t++) {
                float p0 = __expf(sv[2*t]   - mx);
                float p1 = __expf(sv[2*t+1] - mx);
                sum += p0 + p1;
                __half2 hh = __floats2half2_rn(p0, p1);
                pah[t >> 1][(t & 1)*2 + h] = *reinterpret_cast<uint32_t*>(&hh);
            }
            sum += __shfl_xor_sync(0xffffffffu, sum, 1);
            sum += __shfl_xor_sync(0xffffffffu, sum, 2);
            l_[h] = l_[h]*corr + sum;
            m_[h] = mx;
            #pragma unroll
            for (int t = 0; t < 8; t++) {
                o_acc[t][2*h]   *= corr;
                o_acc[t][2*h+1] *= corr;
            }
        }

        // O += P @ V
        #pragma unroll
        for (int c = 0; c < 4; c++) {
            #pragma unroll
            for (int tp = 0; tp < 4; tp++) {
                int row = c*16 + (q8 & 1)*8 + rr;
                int col = tp*16 + (q8 >> 1)*8;
                uint32_t bv[4];
                ldsm4t(bv, sm_u32(vp + row*KPAD + col));
                mma16816(o_acc[2*tp],     pah[c], bv[0], bv[1]);
                mma16816(o_acc[2*tp + 1], pah[c], bv[2], bv[3]);
            }
        }
        __syncthreads();
    }

    // epilogue
    const int b_ = bh / NH, hd = bh % NH;
    const int g  = lane >> 2, nj = (lane & 3)*2;
    #pragma unroll
    for (int h = 0; h < 2; h++) {
        float inv = 1.0f / l_[h];
        int row = q0 + w*16 + g + h*8;
        float* orow = out + (size_t)(b_*SQ + row)*DIM + hd*DH;
        #pragma unroll
        for (int t = 0; t < 8; t++) {
            float2 v2 = make_float2(o_acc[t][2*h]*inv, o_acc[t][2*h+1]*inv);
            *(float2*)(orow + t*8 + nj) = v2;
        }
    }
}

// ---------------------------------------------------------------------------
extern "C" void kernel_launch(void* const* d_in, const int* in_sizes, int n_in,
                              void* d_out, int out_size)
{
    const float* X   = (const float*)d_in[0];
    const float* Wqr = (const float*)d_in[1];
    const float* Wqi = (const float*)d_in[2];
    const float* Wkr = (const float*)d_in[3];
    const float* Wki = (const float*)d_in[4];
    const float* Wv  = (const float*)d_in[5];
    float* out = (float*)d_out;

    const int proj_smem = 2 * PSTG * (int)sizeof(__half);                // 73728
    const int attn_smem = (2*64*KPAD + 2*KVSTG) * (int)sizeof(__half);   // 73728
    cudaFuncSetAttribute(proj_mma_kernel, cudaFuncAttributeMaxDynamicSharedMemorySize, proj_smem);
    cudaFuncSetAttribute(attn_kernel, cudaFuncAttributeMaxDynamicSharedMemorySize, attn_smem);

    split_kernel<<<1024, 256>>>(X, Wqr, Wqi, Wkr, Wki, Wv);
    proj_mma_kernel<<<dim3(30, 32), PTHR, proj_smem>>>();
    attn_kernel<<<dim3(SQ/64, BH), ATHR, attn_smem>>>(out);
}